// round 1
// baseline (speedup 1.0000x reference)
#include <cuda_runtime.h>
#include <math.h>

#define BB   4
#define SS   2048
#define DD   1024
#define HH   16
#define DKK  64
#define DFFN 4096
#define NTOK (BB*SS)          /* 8192 tokens */
#define LNEPS 1e-6f

/* ---------------- scratch (alloc-free: __device__ globals) ---------------- */
__device__ float g_ln1 [NTOK*DD];
__device__ float g_q   [NTOK*DD];
__device__ float g_k   [NTOK*DD];
__device__ float g_v   [NTOK*DD];
__device__ float g_attn[NTOK*DD];
__device__ float g_h   [NTOK*DD];
__device__ float g_ln2 [NTOK*DD];
__device__ float g_ffn [(size_t)NTOK*DFFN];

/* ---------------- LayerNorm (torch-style: unbiased std, eps on std) ------- */
__global__ void ln_kernel(const float* __restrict__ x,
                          const float* __restrict__ ap,
                          const float* __restrict__ cp,
                          float* __restrict__ y) {
    __shared__ float sred[16];
    int row = blockIdx.x;
    int tid = threadIdx.x;               /* 256 threads, 4 floats each = 1024 */
    const float4 v = ((const float4*)(x + (size_t)row*DD))[tid];
    float s  = v.x + v.y + v.z + v.w;
    float sq = v.x*v.x + v.y*v.y + v.z*v.z + v.w*v.w;
    #pragma unroll
    for (int off = 16; off > 0; off >>= 1) {
        s  += __shfl_xor_sync(0xffffffffu, s,  off);
        sq += __shfl_xor_sync(0xffffffffu, sq, off);
    }
    int warp = tid >> 5, lane = tid & 31;
    if (lane == 0) { sred[warp] = s; sred[warp + 8] = sq; }
    __syncthreads();
    float st = 0.f, sqt = 0.f;
    #pragma unroll
    for (int i = 0; i < 8; i++) { st += sred[i]; sqt += sred[i + 8]; }
    float mean = st * (1.0f / DD);
    float var  = (sqt - (float)DD * mean * mean) * (1.0f / (DD - 1));
    float stdv = sqrtf(fmaxf(var, 0.f));
    float inv  = ap[0] / (stdv + LNEPS);
    float beta = cp[0];
    float4 o;
    o.x = (v.x - mean) * inv + beta;
    o.y = (v.y - mean) * inv + beta;
    o.z = (v.z - mean) * inv + beta;
    o.w = (v.w - mean) * inv + beta;
    ((float4*)(y + (size_t)row*DD))[tid] = o;
}

/* ---------------- NT GEMM: C[M,N] = A[M,K] * B[N,K]^T + bias (+res, relu) - */
#define GBM 128
#define GBN 128
#define GBK 16

template<bool RELU, bool RES>
__global__ void __launch_bounds__(256)
gemm_nt(const float* __restrict__ A, const float* __restrict__ Bw,
        const float* __restrict__ bias, const float* __restrict__ res,
        float* __restrict__ C, int M, int N, int K) {
    __shared__ float As[GBK][GBM];
    __shared__ float Bs[GBK][GBN];
    const int tid  = threadIdx.x;
    const int bm   = blockIdx.y, bn = blockIdx.x;
    const int trow = (tid >> 4) * 8;
    const int tcol = (tid & 15) * 8;
    const int lr   = tid >> 2;           /* 0..63 */
    const int lc   = (tid & 3) * 4;      /* 0,4,8,12 */
    float acc[8][8];
    #pragma unroll
    for (int i = 0; i < 8; i++)
        #pragma unroll
        for (int j = 0; j < 8; j++) acc[i][j] = 0.f;

    const float* Ab = A  + (size_t)(bm * GBM) * K;
    const float* Bb = Bw + (size_t)(bn * GBN) * K;

    for (int k0 = 0; k0 < K; k0 += GBK) {
        #pragma unroll
        for (int hh = 0; hh < 2; hh++) {
            int r = lr + hh * 64;
            float4 a4 = *(const float4*)(Ab + (size_t)r*K + k0 + lc);
            As[lc+0][r] = a4.x; As[lc+1][r] = a4.y;
            As[lc+2][r] = a4.z; As[lc+3][r] = a4.w;
            float4 b4 = *(const float4*)(Bb + (size_t)r*K + k0 + lc);
            Bs[lc+0][r] = b4.x; Bs[lc+1][r] = b4.y;
            Bs[lc+2][r] = b4.z; Bs[lc+3][r] = b4.w;
        }
        __syncthreads();
        #pragma unroll
        for (int kk = 0; kk < GBK; kk++) {
            float ar[8], br[8];
            *(float4*)(ar)     = *(const float4*)&As[kk][trow];
            *(float4*)(ar + 4) = *(const float4*)&As[kk][trow + 4];
            *(float4*)(br)     = *(const float4*)&Bs[kk][tcol];
            *(float4*)(br + 4) = *(const float4*)&Bs[kk][tcol + 4];
            #pragma unroll
            for (int i = 0; i < 8; i++)
                #pragma unroll
                for (int j = 0; j < 8; j++)
                    acc[i][j] += ar[i] * br[j];
        }
        __syncthreads();
    }
    const int n0 = bn * GBN + tcol;
    #pragma unroll
    for (int i = 0; i < 8; i++) {
        size_t m = (size_t)(bm * GBM + trow + i);
        float* crow = C + m * N + n0;
        #pragma unroll
        for (int j = 0; j < 8; j += 4) {
            float4 o;
            o.x = acc[i][j+0] + bias[n0+j+0];
            o.y = acc[i][j+1] + bias[n0+j+1];
            o.z = acc[i][j+2] + bias[n0+j+2];
            o.w = acc[i][j+3] + bias[n0+j+3];
            if (RELU) {
                o.x = fmaxf(o.x, 0.f); o.y = fmaxf(o.y, 0.f);
                o.z = fmaxf(o.z, 0.f); o.w = fmaxf(o.w, 0.f);
            }
            if (RES) {
                float4 r4 = *(const float4*)(res + m * N + n0 + j);
                o.x += r4.x; o.y += r4.y; o.z += r4.z; o.w += r4.w;
            }
            *(float4*)(crow + j) = o;
        }
    }
}

/* ---------------- Flash attention: 64 q-rows per CTA, stream 64-key tiles - */
__global__ void __launch_bounds__(256)
flash_kernel(const float* __restrict__ Q, const float* __restrict__ Kg,
             const float* __restrict__ Vg, const int* __restrict__ mask,
             float* __restrict__ O) {
    __shared__ float Qs [64 * 64];
    __shared__ float KPs[64 * 64];     /* holds K^T, then reused for P */
    __shared__ float Vs [64 * 64];

    const int qt = blockIdx.x, h = blockIdx.y, b = blockIdx.z;
    const int tid = threadIdx.x;
    const int ty = tid >> 4, tx = tid & 15;

    /* load Q tile [64 rows][64 dims] */
    const float* qbase = Q + (size_t)(b * SS + qt * 64) * DD + h * DKK;
    #pragma unroll
    for (int it = 0; it < 4; it++) {
        int lin = tid + it * 256;
        int r = lin >> 4, cg = lin & 15;
        float4 v4 = *(const float4*)(qbase + (size_t)r * DD + cg * 4);
        *(float4*)&Qs[r * 64 + cg * 4] = v4;
    }

    float acc[4][4];
    float mrow[4], lrow[4];
    #pragma unroll
    for (int i = 0; i < 4; i++) {
        mrow[i] = -INFINITY; lrow[i] = 0.f;
        #pragma unroll
        for (int j = 0; j < 4; j++) acc[i][j] = 0.f;
    }
    const int* mp = mask + b * SS;

    for (int kt = 0; kt < SS / 64; kt++) {
        __syncthreads();    /* previous-iter P/V readers done; Qs visible on it 0 */
        const float* kbase = Kg + (size_t)(b * SS + kt * 64) * DD + h * DKK;
        const float* vbase = Vg + (size_t)(b * SS + kt * 64) * DD + h * DKK;
        #pragma unroll
        for (int it = 0; it < 4; it++) {
            int lin = tid + it * 256;
            int r = lin >> 4, cg = lin & 15;
            float4 k4 = *(const float4*)(kbase + (size_t)r * DD + cg * 4);
            KPs[(cg*4+0) * 64 + r] = k4.x;   /* store K transposed */
            KPs[(cg*4+1) * 64 + r] = k4.y;
            KPs[(cg*4+2) * 64 + r] = k4.z;
            KPs[(cg*4+3) * 64 + r] = k4.w;
            float4 v4 = *(const float4*)(vbase + (size_t)r * DD + cg * 4);
            *(float4*)&Vs[r * 64 + cg * 4] = v4;
        }
        __syncthreads();

        /* S = Q K^T : thread owns rows 4ty..+3, cols 4tx..+3 */
        float s[4][4];
        #pragma unroll
        for (int i = 0; i < 4; i++)
            #pragma unroll
            for (int j = 0; j < 4; j++) s[i][j] = 0.f;
        #pragma unroll 8
        for (int kk = 0; kk < 64; kk++) {
            float4 kv = *(const float4*)&KPs[kk * 64 + tx * 4];
            float qv[4];
            #pragma unroll
            for (int i = 0; i < 4; i++) qv[i] = Qs[(ty*4 + i) * 64 + kk];
            #pragma unroll
            for (int i = 0; i < 4; i++) {
                s[i][0] += qv[i] * kv.x; s[i][1] += qv[i] * kv.y;
                s[i][2] += qv[i] * kv.z; s[i][3] += qv[i] * kv.w;
            }
        }
        /* scale + mask (exact ref semantics: masked -> -1e9 post-scale) */
        int kc0 = kt * 64 + tx * 4;
        int mj0 = __ldg(mp + kc0 + 0), mj1 = __ldg(mp + kc0 + 1);
        int mj2 = __ldg(mp + kc0 + 2), mj3 = __ldg(mp + kc0 + 3);
        #pragma unroll
        for (int i = 0; i < 4; i++) {
            s[i][0] = mj0 ? s[i][0] * 0.125f : -1e9f;
            s[i][1] = mj1 ? s[i][1] * 0.125f : -1e9f;
            s[i][2] = mj2 ? s[i][2] * 0.125f : -1e9f;
            s[i][3] = mj3 ? s[i][3] * 0.125f : -1e9f;
        }
        /* online softmax per row (reduce across the 16 tx lanes) */
        #pragma unroll
        for (int i = 0; i < 4; i++) {
            float tmax = fmaxf(fmaxf(s[i][0], s[i][1]), fmaxf(s[i][2], s[i][3]));
            #pragma unroll
            for (int off = 8; off > 0; off >>= 1)
                tmax = fmaxf(tmax, __shfl_xor_sync(0xffffffffu, tmax, off));
            float mnew = fmaxf(mrow[i], tmax);
            float corr = __expf(mrow[i] - mnew);
            float psum = 0.f;
            #pragma unroll
            for (int j = 0; j < 4; j++) {
                s[i][j] = __expf(s[i][j] - mnew);
                psum += s[i][j];
            }
            #pragma unroll
            for (int off = 8; off > 0; off >>= 1)
                psum += __shfl_xor_sync(0xffffffffu, psum, off);
            lrow[i] = lrow[i] * corr + psum;
            mrow[i] = mnew;
            #pragma unroll
            for (int j = 0; j < 4; j++) acc[i][j] *= corr;
        }
        __syncthreads();           /* all threads done reading K^T */
        #pragma unroll
        for (int i = 0; i < 4; i++)
            *(float4*)&KPs[(ty*4 + i) * 64 + tx * 4] =
                make_float4(s[i][0], s[i][1], s[i][2], s[i][3]);
        __syncthreads();
        /* O += P V */
        #pragma unroll 4
        for (int j = 0; j < 64; j++) {
            float4 v4 = *(const float4*)&Vs[j * 64 + tx * 4];
            #pragma unroll
            for (int i = 0; i < 4; i++) {
                float p = KPs[(ty*4 + i) * 64 + j];
                acc[i][0] += p * v4.x; acc[i][1] += p * v4.y;
                acc[i][2] += p * v4.z; acc[i][3] += p * v4.w;
            }
        }
    }
    /* normalize + store back to [B,S,H,DK] layout (== token-major D) */
    float* obase = O + (size_t)(b * SS + qt * 64) * DD + h * DKK;
    #pragma unroll
    for (int i = 0; i < 4; i++) {
        float inv = 1.0f / lrow[i];
        float4 o = make_float4(acc[i][0]*inv, acc[i][1]*inv,
                               acc[i][2]*inv, acc[i][3]*inv);
        *(float4*)(obase + (size_t)(ty*4 + i) * DD + tx * 4) = o;
    }
}

/* ---------------- host orchestration (graph-capturable) ------------------- */
extern "C" void kernel_launch(void* const* d_in, const int* in_sizes, int n_in,
                              void* d_out, int out_size) {
    (void)in_sizes; (void)n_in; (void)out_size;
    const float* x    = (const float*)d_in[0];
    const int*   mask = (const int*)  d_in[1];
    const float* wq   = (const float*)d_in[2];
    const float* bq   = (const float*)d_in[3];
    const float* wk   = (const float*)d_in[4];
    const float* bk   = (const float*)d_in[5];
    const float* wv   = (const float*)d_in[6];
    const float* bv   = (const float*)d_in[7];
    const float* wo   = (const float*)d_in[8];
    const float* bo   = (const float*)d_in[9];
    const float* w1   = (const float*)d_in[10];
    const float* b1   = (const float*)d_in[11];
    const float* w2   = (const float*)d_in[12];
    const float* b2   = (const float*)d_in[13];
    const float* a1   = (const float*)d_in[14];
    const float* c1   = (const float*)d_in[15];
    const float* a2   = (const float*)d_in[16];
    const float* c2   = (const float*)d_in[17];
    float* out = (float*)d_out;

    float *ln1, *q, *k, *v, *attn, *h, *ln2, *ffn;
    cudaGetSymbolAddress((void**)&ln1,  g_ln1);
    cudaGetSymbolAddress((void**)&q,    g_q);
    cudaGetSymbolAddress((void**)&k,    g_k);
    cudaGetSymbolAddress((void**)&v,    g_v);
    cudaGetSymbolAddress((void**)&attn, g_attn);
    cudaGetSymbolAddress((void**)&h,    g_h);
    cudaGetSymbolAddress((void**)&ln2,  g_ln2);
    cudaGetSymbolAddress((void**)&ffn,  g_ffn);

    /* LN1 */
    ln_kernel<<<NTOK, 256>>>(x, a1, c1, ln1);
    /* Q,K,V projections */
    dim3 gq(DD / GBN, NTOK / GBM);
    gemm_nt<false,false><<<gq, 256>>>(ln1, wq, bq, nullptr, q,  NTOK, DD, DD);
    gemm_nt<false,false><<<gq, 256>>>(ln1, wk, bk, nullptr, k,  NTOK, DD, DD);
    gemm_nt<false,false><<<gq, 256>>>(ln1, wv, bv, nullptr, v,  NTOK, DD, DD);
    /* attention */
    flash_kernel<<<dim3(SS / 64, HH, BB), 256>>>(q, k, v, mask, attn);
    /* h = x + attn @ wo^T + bo */
    gemm_nt<false,true><<<gq, 256>>>(attn, wo, bo, x, h, NTOK, DD, DD);
    /* LN2 */
    ln_kernel<<<NTOK, 256>>>(h, a2, c2, ln2);
    /* ffn mid = relu(ln2 @ w1^T + b1) */
    gemm_nt<true,false><<<dim3(DFFN / GBN, NTOK / GBM), 256>>>(
        ln2, w1, b1, nullptr, ffn, NTOK, DFFN, DD);
    /* out = h + ffn @ w2^T + b2 */
    gemm_nt<false,true><<<gq, 256>>>(ffn, w2, b2, h, out, NTOK, DD, DFFN);
}

// round 4
// speedup vs baseline: 1.7448x; 1.7448x over previous
#include <cuda_runtime.h>
#include <math.h>
#include <stdint.h>

#define BB   4
#define SS   2048
#define DD   1024
#define HH   16
#define DKK  64
#define DFFN 4096
#define NTOK (BB*SS)          /* 8192 tokens */
#define LNEPS 1e-6f

/* ---------------- scratch (alloc-free: __device__ globals) ---------------- */
__device__ float g_ln1 [NTOK*DD];
__device__ float g_q   [NTOK*DD];
__device__ float g_k   [NTOK*DD];
__device__ float g_v   [NTOK*DD];
__device__ float g_attn[NTOK*DD];
__device__ float g_h   [NTOK*DD];
__device__ float g_ln2 [NTOK*DD];
__device__ float g_ffn [(size_t)NTOK*DFFN];

/* ---------------- LayerNorm (torch-style: unbiased std, eps on std) ------- */
__global__ void ln_kernel(const float* __restrict__ x,
                          const float* __restrict__ ap,
                          const float* __restrict__ cp,
                          float* __restrict__ y) {
    __shared__ float sred[16];
    int row = blockIdx.x;
    int tid = threadIdx.x;               /* 256 threads, 4 floats each = 1024 */
    const float4 v = ((const float4*)(x + (size_t)row*DD))[tid];
    float s  = v.x + v.y + v.z + v.w;
    float sq = v.x*v.x + v.y*v.y + v.z*v.z + v.w*v.w;
    #pragma unroll
    for (int off = 16; off > 0; off >>= 1) {
        s  += __shfl_xor_sync(0xffffffffu, s,  off);
        sq += __shfl_xor_sync(0xffffffffu, sq, off);
    }
    int warp = tid >> 5, lane = tid & 31;
    if (lane == 0) { sred[warp] = s; sred[warp + 8] = sq; }
    __syncthreads();
    float st = 0.f, sqt = 0.f;
    #pragma unroll
    for (int i = 0; i < 8; i++) { st += sred[i]; sqt += sred[i + 8]; }
    float mean = st * (1.0f / DD);
    float var  = (sqt - (float)DD * mean * mean) * (1.0f / (DD - 1));
    float stdv = sqrtf(fmaxf(var, 0.f));
    float inv  = ap[0] / (stdv + LNEPS);
    float beta = cp[0];
    float4 o;
    o.x = (v.x - mean) * inv + beta;
    o.y = (v.y - mean) * inv + beta;
    o.z = (v.z - mean) * inv + beta;
    o.w = (v.w - mean) * inv + beta;
    ((float4*)(y + (size_t)row*DD))[tid] = o;
}

/* ---------------- TF32 helpers -------------------------------------------- */
__device__ __forceinline__ uint32_t f2tf32(float f) {
    uint32_t u;
    asm("cvt.rna.tf32.f32 %0, %1;" : "=r"(u) : "f"(f));
    return u;
}

__device__ __forceinline__ void mma_tf32(float* c, const uint32_t* a, const uint32_t* b) {
    asm volatile(
        "mma.sync.aligned.m16n8k8.row.col.f32.tf32.tf32.f32 "
        "{%0,%1,%2,%3}, {%4,%5,%6,%7}, {%8,%9}, {%0,%1,%2,%3};"
        : "+f"(c[0]), "+f"(c[1]), "+f"(c[2]), "+f"(c[3])
        : "r"(a[0]), "r"(a[1]), "r"(a[2]), "r"(a[3]), "r"(b[0]), "r"(b[1]));
}

/* ---------------- TF32 tensor-core NT GEMM: C = A[M,K] * B[N,K]^T + bias -- */
/* CTA tile 128x128, 8 warps in 2(m)x4(n), warp tile 64x32, BK=16.           */
/* smem stride padded to 20 floats -> conflict-free fragment LDS.            */
#define TBM 128
#define TBN 128
#define TBK 16
#define TPAD 20

template<bool RELU, bool RES>
__global__ void __launch_bounds__(256)
gemm_tc(const float* __restrict__ A, const float* __restrict__ Bw,
        const float* __restrict__ bias, const float* __restrict__ res,
        float* __restrict__ C, int M, int N, int K) {
    __shared__ uint32_t As[TBM * TPAD];
    __shared__ uint32_t Bs[TBN * TPAD];

    const int tid  = threadIdx.x;
    const int warp = tid >> 5, lane = tid & 31;
    const int g = lane >> 2;          /* group id 0..7   */
    const int t = lane & 3;           /* tid in group    */
    const int wm = warp & 1;          /* warp m coord 0..1 */
    const int wn = warp >> 1;         /* warp n coord 0..3 */
    const int bm = blockIdx.y, bn = blockIdx.x;

    /* gmem load coords: each thread loads 2 float4 rows for A and B */
    const int lr = tid >> 2;          /* 0..63 */
    const int lc = (tid & 3) * 4;     /* 0,4,8,12 */
    const float* Ab = A  + (size_t)(bm * TBM) * K;
    const float* Bb = Bw + (size_t)(bn * TBN) * K;

    float acc[4][4][4];
    #pragma unroll
    for (int i = 0; i < 4; i++)
        #pragma unroll
        for (int j = 0; j < 4; j++)
            #pragma unroll
            for (int e = 0; e < 4; e++) acc[i][j][e] = 0.f;

    for (int k0 = 0; k0 < K; k0 += TBK) {
        /* stage gmem -> smem with TF32 rounding */
        #pragma unroll
        for (int hh = 0; hh < 2; hh++) {
            int r = lr + hh * 64;
            float4 a4 = *(const float4*)(Ab + (size_t)r * K + k0 + lc);
            As[r * TPAD + lc + 0] = f2tf32(a4.x);
            As[r * TPAD + lc + 1] = f2tf32(a4.y);
            As[r * TPAD + lc + 2] = f2tf32(a4.z);
            As[r * TPAD + lc + 3] = f2tf32(a4.w);
            float4 b4 = *(const float4*)(Bb + (size_t)r * K + k0 + lc);
            Bs[r * TPAD + lc + 0] = f2tf32(b4.x);
            Bs[r * TPAD + lc + 1] = f2tf32(b4.y);
            Bs[r * TPAD + lc + 2] = f2tf32(b4.z);
            Bs[r * TPAD + lc + 3] = f2tf32(b4.w);
        }
        __syncthreads();

        #pragma unroll
        for (int ks = 0; ks < TBK; ks += 8) {
            uint32_t af[4][4], bf[4][2];
            #pragma unroll
            for (int mt = 0; mt < 4; mt++) {
                int m0 = wm * 64 + mt * 16;
                af[mt][0] = As[(m0 + g    ) * TPAD + ks + t    ];
                af[mt][1] = As[(m0 + g + 8) * TPAD + ks + t    ];
                af[mt][2] = As[(m0 + g    ) * TPAD + ks + t + 4];
                af[mt][3] = As[(m0 + g + 8) * TPAD + ks + t + 4];
            }
            #pragma unroll
            for (int nt = 0; nt < 4; nt++) {
                int n0 = wn * 32 + nt * 8;
                bf[nt][0] = Bs[(n0 + g) * TPAD + ks + t    ];
                bf[nt][1] = Bs[(n0 + g) * TPAD + ks + t + 4];
            }
            #pragma unroll
            for (int mt = 0; mt < 4; mt++)
                #pragma unroll
                for (int nt = 0; nt < 4; nt++)
                    mma_tf32(acc[mt][nt], af[mt], bf[nt]);
        }
        __syncthreads();
    }

    /* epilogue: bias (+relu) (+residual), write float2 pairs */
    #pragma unroll
    for (int mt = 0; mt < 4; mt++) {
        #pragma unroll
        for (int nt = 0; nt < 4; nt++) {
            int col = bn * TBN + wn * 32 + nt * 8 + t * 2;
            float bx = bias[col], by = bias[col + 1];
            #pragma unroll
            for (int half = 0; half < 2; half++) {
                size_t row = (size_t)(bm * TBM + wm * 64 + mt * 16 + g + half * 8);
                float ox = acc[mt][nt][half * 2 + 0] + bx;
                float oy = acc[mt][nt][half * 2 + 1] + by;
                if (RELU) { ox = fmaxf(ox, 0.f); oy = fmaxf(oy, 0.f); }
                if (RES) {
                    float2 r2 = *(const float2*)(res + row * N + col);
                    ox += r2.x; oy += r2.y;
                }
                *(float2*)(C + row * N + col) = make_float2(ox, oy);
            }
        }
    }
}

/* ---------------- Flash attention: 64 q-rows per CTA, stream 64-key tiles - */
__global__ void __launch_bounds__(256)
flash_kernel(const float* __restrict__ Q, const float* __restrict__ Kg,
             const float* __restrict__ Vg, const int* __restrict__ mask,
             float* __restrict__ O) {
    __shared__ float Qs [64 * 64];
    __shared__ float KPs[64 * 64];     /* holds K^T, then reused for P */
    __shared__ float Vs [64 * 64];

    const int qt = blockIdx.x, h = blockIdx.y, b = blockIdx.z;
    const int tid = threadIdx.x;
    const int ty = tid >> 4, tx = tid & 15;

    /* load Q tile [64 rows][64 dims] */
    const float* qbase = Q + (size_t)(b * SS + qt * 64) * DD + h * DKK;
    #pragma unroll
    for (int it = 0; it < 4; it++) {
        int lin = tid + it * 256;
        int r = lin >> 4, cg = lin & 15;
        float4 v4 = *(const float4*)(qbase + (size_t)r * DD + cg * 4);
        *(float4*)&Qs[r * 64 + cg * 4] = v4;
    }

    float acc[4][4];
    float mrow[4], lrow[4];
    #pragma unroll
    for (int i = 0; i < 4; i++) {
        mrow[i] = -INFINITY; lrow[i] = 0.f;
        #pragma unroll
        for (int j = 0; j < 4; j++) acc[i][j] = 0.f;
    }
    const int* mp = mask + b * SS;

    for (int kt = 0; kt < SS / 64; kt++) {
        __syncthreads();    /* previous-iter P/V readers done; Qs visible on it 0 */
        const float* kbase = Kg + (size_t)(b * SS + kt * 64) * DD + h * DKK;
        const float* vbase = Vg + (size_t)(b * SS + kt * 64) * DD + h * DKK;
        #pragma unroll
        for (int it = 0; it < 4; it++) {
            int lin = tid + it * 256;
            int r = lin >> 4, cg = lin & 15;
            float4 k4 = *(const float4*)(kbase + (size_t)r * DD + cg * 4);
            KPs[(cg*4+0) * 64 + r] = k4.x;   /* store K transposed */
            KPs[(cg*4+1) * 64 + r] = k4.y;
            KPs[(cg*4+2) * 64 + r] = k4.z;
            KPs[(cg*4+3) * 64 + r] = k4.w;
            float4 v4 = *(const float4*)(vbase + (size_t)r * DD + cg * 4);
            *(float4*)&Vs[r * 64 + cg * 4] = v4;
        }
        __syncthreads();

        /* S = Q K^T : thread owns rows 4ty..+3, cols 4tx..+3 */
        float s[4][4];
        #pragma unroll
        for (int i = 0; i < 4; i++)
            #pragma unroll
            for (int j = 0; j < 4; j++) s[i][j] = 0.f;
        #pragma unroll 8
        for (int kk = 0; kk < 64; kk++) {
            float4 kv = *(const float4*)&KPs[kk * 64 + tx * 4];
            float qv[4];
            #pragma unroll
            for (int i = 0; i < 4; i++) qv[i] = Qs[(ty*4 + i) * 64 + kk];
            #pragma unroll
            for (int i = 0; i < 4; i++) {
                s[i][0] += qv[i] * kv.x; s[i][1] += qv[i] * kv.y;
                s[i][2] += qv[i] * kv.z; s[i][3] += qv[i] * kv.w;
            }
        }
        /* scale + mask (exact ref semantics: masked -> -1e9 post-scale) */
        int kc0 = kt * 64 + tx * 4;
        int mj0 = __ldg(mp + kc0 + 0), mj1 = __ldg(mp + kc0 + 1);
        int mj2 = __ldg(mp + kc0 + 2), mj3 = __ldg(mp + kc0 + 3);
        #pragma unroll
        for (int i = 0; i < 4; i++) {
            s[i][0] = mj0 ? s[i][0] * 0.125f : -1e9f;
            s[i][1] = mj1 ? s[i][1] * 0.125f : -1e9f;
            s[i][2] = mj2 ? s[i][2] * 0.125f : -1e9f;
            s[i][3] = mj3 ? s[i][3] * 0.125f : -1e9f;
        }
        /* online softmax per row (reduce across the 16 tx lanes) */
        #pragma unroll
        for (int i = 0; i < 4; i++) {
            float tmax = fmaxf(fmaxf(s[i][0], s[i][1]), fmaxf(s[i][2], s[i][3]));
            #pragma unroll
            for (int off = 8; off > 0; off >>= 1)
                tmax = fmaxf(tmax, __shfl_xor_sync(0xffffffffu, tmax, off));
            float mnew = fmaxf(mrow[i], tmax);
            float corr = __expf(mrow[i] - mnew);
            float psum = 0.f;
            #pragma unroll
            for (int j = 0; j < 4; j++) {
                s[i][j] = __expf(s[i][j] - mnew);
                psum += s[i][j];
            }
            #pragma unroll
            for (int off = 8; off > 0; off >>= 1)
                psum += __shfl_xor_sync(0xffffffffu, psum, off);
            lrow[i] = lrow[i] * corr + psum;
            mrow[i] = mnew;
            #pragma unroll
            for (int j = 0; j < 4; j++) acc[i][j] *= corr;
        }
        __syncthreads();           /* all threads done reading K^T */
        #pragma unroll
        for (int i = 0; i < 4; i++)
            *(float4*)&KPs[(ty*4 + i) * 64 + tx * 4] =
                make_float4(s[i][0], s[i][1], s[i][2], s[i][3]);
        __syncthreads();
        /* O += P V */
        #pragma unroll 4
        for (int j = 0; j < 64; j++) {
            float4 v4 = *(const float4*)&Vs[j * 64 + tx * 4];
            #pragma unroll
            for (int i = 0; i < 4; i++) {
                float p = KPs[(ty*4 + i) * 64 + j];
                acc[i][0] += p * v4.x; acc[i][1] += p * v4.y;
                acc[i][2] += p * v4.z; acc[i][3] += p * v4.w;
            }
        }
    }
    /* normalize + store back to [B,S,H,DK] layout (== token-major D) */
    float* obase = O + (size_t)(b * SS + qt * 64) * DD + h * DKK;
    #pragma unroll
    for (int i = 0; i < 4; i++) {
        float inv = 1.0f / lrow[i];
        float4 o = make_float4(acc[i][0]*inv, acc[i][1]*inv,
                               acc[i][2]*inv, acc[i][3]*inv);
        *(float4*)(obase + (size_t)(ty*4 + i) * DD + tx * 4) = o;
    }
}

/* ---------------- host orchestration (graph-capturable) ------------------- */
extern "C" void kernel_launch(void* const* d_in, const int* in_sizes, int n_in,
                              void* d_out, int out_size) {
    (void)in_sizes; (void)n_in; (void)out_size;
    const float* x    = (const float*)d_in[0];
    const int*   mask = (const int*)  d_in[1];
    const float* wq   = (const float*)d_in[2];
    const float* bq   = (const float*)d_in[3];
    const float* wk   = (const float*)d_in[4];
    const float* bk   = (const float*)d_in[5];
    const float* wv   = (const float*)d_in[6];
    const float* bv   = (const float*)d_in[7];
    const float* wo   = (const float*)d_in[8];
    const float* bo   = (const float*)d_in[9];
    const float* w1   = (const float*)d_in[10];
    const float* b1   = (const float*)d_in[11];
    const float* w2   = (const float*)d_in[12];
    const float* b2   = (const float*)d_in[13];
    const float* a1   = (const float*)d_in[14];
    const float* c1   = (const float*)d_in[15];
    const float* a2   = (const float*)d_in[16];
    const float* c2   = (const float*)d_in[17];
    float* out = (float*)d_out;

    float *ln1, *q, *k, *v, *attn, *h, *ln2, *ffn;
    cudaGetSymbolAddress((void**)&ln1,  g_ln1);
    cudaGetSymbolAddress((void**)&q,    g_q);
    cudaGetSymbolAddress((void**)&k,    g_k);
    cudaGetSymbolAddress((void**)&v,    g_v);
    cudaGetSymbolAddress((void**)&attn, g_attn);
    cudaGetSymbolAddress((void**)&h,    g_h);
    cudaGetSymbolAddress((void**)&ln2,  g_ln2);
    cudaGetSymbolAddress((void**)&ffn,  g_ffn);

    /* LN1 */
    ln_kernel<<<NTOK, 256>>>(x, a1, c1, ln1);
    /* Q,K,V projections */
    dim3 gq(DD / TBN, NTOK / TBM);
    gemm_tc<false,false><<<gq, 256>>>(ln1, wq, bq, nullptr, q,  NTOK, DD, DD);
    gemm_tc<false,false><<<gq, 256>>>(ln1, wk, bk, nullptr, k,  NTOK, DD, DD);
    gemm_tc<false,false><<<gq, 256>>>(ln1, wv, bv, nullptr, v,  NTOK, DD, DD);
    /* attention */
    flash_kernel<<<dim3(SS / 64, HH, BB), 256>>>(q, k, v, mask, attn);
    /* h = x + attn @ wo^T + bo */
    gemm_tc<false,true><<<gq, 256>>>(attn, wo, bo, x, h, NTOK, DD, DD);
    /* LN2 */
    ln_kernel<<<NTOK, 256>>>(h, a2, c2, ln2);
    /* ffn mid = relu(ln2 @ w1^T + b1) */
    gemm_tc<true,false><<<dim3(DFFN / TBN, NTOK / TBM), 256>>>(
        ln2, w1, b1, nullptr, ffn, NTOK, DFFN, DD);
    /* out = h + ffn @ w2^T + b2 */
    gemm_tc<false,true><<<gq, 256>>>(ffn, w2, b2, h, out, NTOK, DD, DFFN);
}

// round 5
// speedup vs baseline: 2.9671x; 1.7005x over previous
#include <cuda_runtime.h>
#include <math.h>
#include <stdint.h>

#define BB   4
#define SS   2048
#define DD   1024
#define HH   16
#define DKK  64
#define DFFN 4096
#define NTOK (BB*SS)          /* 8192 tokens */
#define LNEPS 1e-6f

/* ---------------- scratch (alloc-free: __device__ globals) ---------------- */
__device__ float g_ln1 [NTOK*DD];
__device__ float g_q   [NTOK*DD];
__device__ float g_k   [NTOK*DD];
__device__ float g_v   [NTOK*DD];
__device__ float g_attn[NTOK*DD];
__device__ float g_h   [NTOK*DD];
__device__ float g_ln2 [NTOK*DD];
__device__ float g_ffn [(size_t)NTOK*DFFN];
/* tf32-rounded weights */
__device__ float g_wqc[DD*DD];
__device__ float g_wkc[DD*DD];
__device__ float g_wvc[DD*DD];
__device__ float g_woc[DD*DD];
__device__ float g_w1c[DFFN*DD];
__device__ float g_w2c[DD*DFFN];

/* ---------------- TF32 helpers -------------------------------------------- */
__device__ __forceinline__ uint32_t f2tf32(float f) {
    uint32_t u;
    asm("cvt.rna.tf32.f32 %0, %1;" : "=r"(u) : "f"(f));
    return u;
}
__device__ __forceinline__ float tf32r(float f) {
    return __uint_as_float(f2tf32(f));
}
__device__ __forceinline__ void mma_tf32(float* c, const uint32_t* a, const uint32_t* b) {
    asm volatile(
        "mma.sync.aligned.m16n8k8.row.col.f32.tf32.tf32.f32 "
        "{%0,%1,%2,%3}, {%4,%5,%6,%7}, {%8,%9}, {%0,%1,%2,%3};"
        : "+f"(c[0]), "+f"(c[1]), "+f"(c[2]), "+f"(c[3])
        : "r"(a[0]), "r"(a[1]), "r"(a[2]), "r"(a[3]), "r"(b[0]), "r"(b[1]));
}
__device__ __forceinline__ void cp16(void* smem, const void* g) {
    uint32_t s = (uint32_t)__cvta_generic_to_shared(smem);
    asm volatile("cp.async.cg.shared.global [%0], [%1], 16;" :: "r"(s), "l"(g));
}

/* ---------------- weight pre-rounding kernel ------------------------------ */
__global__ void cvt_tf32_kernel(const float* __restrict__ src,
                                float* __restrict__ dst, int n4) {
    int i = blockIdx.x * 256 + threadIdx.x;
    if (i < n4) {
        float4 v = ((const float4*)src)[i];
        float4 o;
        o.x = tf32r(v.x); o.y = tf32r(v.y); o.z = tf32r(v.z); o.w = tf32r(v.w);
        ((float4*)dst)[i] = o;
    }
}

/* ---------------- LayerNorm (tf32-rounded output: feeds GEMMs only) ------- */
__global__ void ln_kernel(const float* __restrict__ x,
                          const float* __restrict__ ap,
                          const float* __restrict__ cp,
                          float* __restrict__ y) {
    __shared__ float sred[16];
    int row = blockIdx.x;
    int tid = threadIdx.x;
    const float4 v = ((const float4*)(x + (size_t)row*DD))[tid];
    float s  = v.x + v.y + v.z + v.w;
    float sq = v.x*v.x + v.y*v.y + v.z*v.z + v.w*v.w;
    #pragma unroll
    for (int off = 16; off > 0; off >>= 1) {
        s  += __shfl_xor_sync(0xffffffffu, s,  off);
        sq += __shfl_xor_sync(0xffffffffu, sq, off);
    }
    int warp = tid >> 5, lane = tid & 31;
    if (lane == 0) { sred[warp] = s; sred[warp + 8] = sq; }
    __syncthreads();
    float st = 0.f, sqt = 0.f;
    #pragma unroll
    for (int i = 0; i < 8; i++) { st += sred[i]; sqt += sred[i + 8]; }
    float mean = st * (1.0f / DD);
    float var  = (sqt - (float)DD * mean * mean) * (1.0f / (DD - 1));
    float stdv = sqrtf(fmaxf(var, 0.f));
    float inv  = ap[0] / (stdv + LNEPS);
    float beta = cp[0];
    float4 o;
    o.x = tf32r((v.x - mean) * inv + beta);
    o.y = tf32r((v.y - mean) * inv + beta);
    o.z = tf32r((v.z - mean) * inv + beta);
    o.w = tf32r((v.w - mean) * inv + beta);
    ((float4*)(y + (size_t)row*DD))[tid] = o;
}

/* ---------------- TF32 TC NT GEMM, cp.async double buffered --------------- */
/* C = A[M,K] * B[N,K]^T + bias (+relu)(+res). A,B pre-rounded to tf32.      */
#define TBM 128
#define TBN 128
#define TBK 16
#define TPAD 20     /* 80B row stride: 16B-aligned, conflict-free frags */

template<bool RELU, bool RES, bool TFOUT>
__global__ void __launch_bounds__(256)
gemm_tc(const float* __restrict__ A, const float* __restrict__ Bw,
        const float* __restrict__ bias, const float* __restrict__ res,
        float* __restrict__ C, int M, int N, int K) {
    __shared__ float As[2][TBM * TPAD];
    __shared__ float Bs[2][TBN * TPAD];

    const int tid  = threadIdx.x;
    const int warp = tid >> 5, lane = tid & 31;
    const int g = lane >> 2, t = lane & 3;
    const int wm = warp & 1, wn = warp >> 1;
    const int bm = blockIdx.y, bn = blockIdx.x;
    const int lr = tid >> 2, lc = (tid & 3) * 4;

    const float* Ab = A  + (size_t)(bm * TBM) * K;
    const float* Bb = Bw + (size_t)(bn * TBN) * K;

    float acc[4][4][4] = {};
    const int ntiles = K / TBK;

    /* stage tile 0 */
    cp16(&As[0][lr * TPAD + lc],        Ab + (size_t)lr * K + lc);
    cp16(&As[0][(lr + 64) * TPAD + lc], Ab + (size_t)(lr + 64) * K + lc);
    cp16(&Bs[0][lr * TPAD + lc],        Bb + (size_t)lr * K + lc);
    cp16(&Bs[0][(lr + 64) * TPAD + lc], Bb + (size_t)(lr + 64) * K + lc);
    asm volatile("cp.async.commit_group;");

    for (int kt = 0; kt < ntiles; kt++) {
        if (kt + 1 < ntiles) {
            int nb = (kt + 1) & 1, ko = (kt + 1) * TBK;
            cp16(&As[nb][lr * TPAD + lc],        Ab + (size_t)lr * K + ko + lc);
            cp16(&As[nb][(lr + 64) * TPAD + lc], Ab + (size_t)(lr + 64) * K + ko + lc);
            cp16(&Bs[nb][lr * TPAD + lc],        Bb + (size_t)lr * K + ko + lc);
            cp16(&Bs[nb][(lr + 64) * TPAD + lc], Bb + (size_t)(lr + 64) * K + ko + lc);
        }
        asm volatile("cp.async.commit_group;");
        asm volatile("cp.async.wait_group 1;");
        __syncthreads();
        const float* Ac = As[kt & 1];
        const float* Bc = Bs[kt & 1];
        #pragma unroll
        for (int ks = 0; ks < TBK; ks += 8) {
            uint32_t af[4][4], bf[4][2];
            #pragma unroll
            for (int mt = 0; mt < 4; mt++) {
                int m0 = wm * 64 + mt * 16;
                af[mt][0] = __float_as_uint(Ac[(m0 + g    ) * TPAD + ks + t    ]);
                af[mt][1] = __float_as_uint(Ac[(m0 + g + 8) * TPAD + ks + t    ]);
                af[mt][2] = __float_as_uint(Ac[(m0 + g    ) * TPAD + ks + t + 4]);
                af[mt][3] = __float_as_uint(Ac[(m0 + g + 8) * TPAD + ks + t + 4]);
            }
            #pragma unroll
            for (int nt = 0; nt < 4; nt++) {
                int n0 = wn * 32 + nt * 8;
                bf[nt][0] = __float_as_uint(Bc[(n0 + g) * TPAD + ks + t    ]);
                bf[nt][1] = __float_as_uint(Bc[(n0 + g) * TPAD + ks + t + 4]);
            }
            #pragma unroll
            for (int mt = 0; mt < 4; mt++)
                #pragma unroll
                for (int nt = 0; nt < 4; nt++)
                    mma_tf32(acc[mt][nt], af[mt], bf[nt]);
        }
        __syncthreads();
    }

    /* epilogue */
    #pragma unroll
    for (int mt = 0; mt < 4; mt++) {
        #pragma unroll
        for (int nt = 0; nt < 4; nt++) {
            int col = bn * TBN + wn * 32 + nt * 8 + t * 2;
            float bx = bias[col], by = bias[col + 1];
            #pragma unroll
            for (int half = 0; half < 2; half++) {
                size_t row = (size_t)(bm * TBM + wm * 64 + mt * 16 + g + half * 8);
                float ox = acc[mt][nt][half * 2 + 0] + bx;
                float oy = acc[mt][nt][half * 2 + 1] + by;
                if (RELU) { ox = fmaxf(ox, 0.f); oy = fmaxf(oy, 0.f); }
                if (TFOUT) { ox = tf32r(ox); oy = tf32r(oy); }
                if (RES) {
                    float2 r2 = *(const float2*)(res + row * N + col);
                    ox += r2.x; oy += r2.y;
                }
                *(float2*)(C + row * N + col) = make_float2(ox, oy);
            }
        }
    }
}

/* ---------------- TF32 flash attention ------------------------------------ */
/* CTA: 128 q-rows x full KV stream in 64-key tiles. 8 warps, warp = m16 tile */
#define FBM 128
#define FBN 64
#define FP  68                      /* smem row stride (floats) */
#define FNT (SS / FBN)              /* 32 key tiles */
#define FSMEM ((FBM + 2 * FBN) * FP * 4)

__global__ void __launch_bounds__(256, 1)
flash_tc(const float* __restrict__ Q, const float* __restrict__ Kg,
         const float* __restrict__ Vg, const int* __restrict__ mask,
         float* __restrict__ O) {
    extern __shared__ float fs[];
    float* Qs = fs;                       /* [128][FP], reused as Ps */
    float* Ks = fs + FBM * FP;            /* [64][FP]  (key-major)   */
    float* Vt = fs + (FBM + FBN) * FP;    /* [64][FP]  (dk-major, swizzled) */

    const int qt = blockIdx.x, h = blockIdx.y, b = blockIdx.z;
    const int tid = threadIdx.x;
    const int w = tid >> 5, lane = tid & 31, g = lane >> 2, t = lane & 3;

    /* ---- load Q tile, build register fragments ---- */
    const float* qb = Q + (size_t)(b * SS + qt * FBM) * DD + h * DKK;
    #pragma unroll
    for (int it = 0; it < 8; it++) {
        int lin = tid + it * 256;
        int r = lin >> 4, cg = (lin & 15) * 4;
        *(float4*)&Qs[r * FP + cg] = *(const float4*)(qb + (size_t)r * DD + cg);
    }
    __syncthreads();
    uint32_t qf[8][4];
    {
        int r0 = w * 16 + g;
        #pragma unroll
        for (int ks = 0; ks < 8; ks++) {
            qf[ks][0] = __float_as_uint(Qs[ r0      * FP + ks * 8 + t    ]);
            qf[ks][1] = __float_as_uint(Qs[(r0 + 8) * FP + ks * 8 + t    ]);
            qf[ks][2] = __float_as_uint(Qs[ r0      * FP + ks * 8 + t + 4]);
            qf[ks][3] = __float_as_uint(Qs[(r0 + 8) * FP + ks * 8 + t + 4]);
        }
    }
    __syncthreads();
    float* Ps = Qs;                       /* Q staging area freed -> P tile */

    float oacc[8][4] = {};
    float mrow0 = -1e30f, mrow1 = -1e30f, lrow0 = 0.f, lrow1 = 0.f;

    /* K/V register prefetch: thread owns key-row kr, 16 dk cols at kc */
    const int kr = tid >> 2;
    const int kc = (tid & 3) * 16;
    const float* kb = Kg + (size_t)(b * SS) * DD + h * DKK;
    const float* vb = Vg + (size_t)(b * SS) * DD + h * DKK;
    float4 kpre[4], vpre[4];
    #pragma unroll
    for (int j = 0; j < 4; j++) {
        kpre[j] = *(const float4*)(kb + (size_t)kr * DD + kc + j * 4);
        vpre[j] = *(const float4*)(vb + (size_t)kr * DD + kc + j * 4);
    }
    const int* mp = mask + b * SS;

    for (int kt = 0; kt < FNT; kt++) {
        /* commit staged K (straight) and V (transposed + XOR swizzle) */
        #pragma unroll
        for (int j = 0; j < 4; j++)
            *(float4*)&Ks[kr * FP + kc + j * 4] = kpre[j];
        #pragma unroll
        for (int j = 0; j < 4; j++) {
            int c = kc + j * 4;
            Vt[(c+0) * FP + (kr ^ ((((c+0) >> 4) & 3) << 3))] = vpre[j].x;
            Vt[(c+1) * FP + (kr ^ ((((c+1) >> 4) & 3) << 3))] = vpre[j].y;
            Vt[(c+2) * FP + (kr ^ ((((c+2) >> 4) & 3) << 3))] = vpre[j].z;
            Vt[(c+3) * FP + (kr ^ ((((c+3) >> 4) & 3) << 3))] = vpre[j].w;
        }
        __syncthreads();
        /* prefetch next tile (latency hidden behind mma below) */
        if (kt + 1 < FNT) {
            const float* kn = kb + (size_t)((kt + 1) * FBN + kr) * DD + kc;
            const float* vn = vb + (size_t)((kt + 1) * FBN + kr) * DD + kc;
            #pragma unroll
            for (int j = 0; j < 4; j++) {
                kpre[j] = *(const float4*)(kn + j * 4);
                vpre[j] = *(const float4*)(vn + j * 4);
            }
        }
        /* mask regs for this tile */
        int mk0[8], mk1[8];
        #pragma unroll
        for (int nt = 0; nt < 8; nt++) {
            mk0[nt] = __ldg(mp + kt * FBN + nt * 8 + 2 * t);
            mk1[nt] = __ldg(mp + kt * FBN + nt * 8 + 2 * t + 1);
        }
        /* S = Q K^T */
        float sacc[8][4] = {};
        #pragma unroll
        for (int ks = 0; ks < 8; ks++) {
            #pragma unroll
            for (int nt = 0; nt < 8; nt++) {
                uint32_t bf[2];
                bf[0] = __float_as_uint(Ks[(nt * 8 + g) * FP + ks * 8 + t    ]);
                bf[1] = __float_as_uint(Ks[(nt * 8 + g) * FP + ks * 8 + t + 4]);
                mma_tf32(sacc[nt], qf[ks], bf);
            }
        }
        /* scale + mask (ref: masked -> exactly -1e9 post-scale) */
        #pragma unroll
        for (int nt = 0; nt < 8; nt++) {
            sacc[nt][0] = mk0[nt] ? sacc[nt][0] * 0.125f : -1e9f;
            sacc[nt][1] = mk1[nt] ? sacc[nt][1] * 0.125f : -1e9f;
            sacc[nt][2] = mk0[nt] ? sacc[nt][2] * 0.125f : -1e9f;
            sacc[nt][3] = mk1[nt] ? sacc[nt][3] * 0.125f : -1e9f;
        }
        /* online softmax: this thread owns rows g and g+8 of warp tile */
        float tm0 = -1e30f, tm1 = -1e30f;
        #pragma unroll
        for (int nt = 0; nt < 8; nt++) {
            tm0 = fmaxf(tm0, fmaxf(sacc[nt][0], sacc[nt][1]));
            tm1 = fmaxf(tm1, fmaxf(sacc[nt][2], sacc[nt][3]));
        }
        tm0 = fmaxf(tm0, __shfl_xor_sync(0xffffffffu, tm0, 1));
        tm0 = fmaxf(tm0, __shfl_xor_sync(0xffffffffu, tm0, 2));
        tm1 = fmaxf(tm1, __shfl_xor_sync(0xffffffffu, tm1, 1));
        tm1 = fmaxf(tm1, __shfl_xor_sync(0xffffffffu, tm1, 2));
        float mn0 = fmaxf(mrow0, tm0), mn1 = fmaxf(mrow1, tm1);
        float cr0 = __expf(mrow0 - mn0), cr1 = __expf(mrow1 - mn1);
        float sum0 = 0.f, sum1 = 0.f;
        #pragma unroll
        for (int nt = 0; nt < 8; nt++) {
            sacc[nt][0] = __expf(sacc[nt][0] - mn0);
            sacc[nt][1] = __expf(sacc[nt][1] - mn0);
            sacc[nt][2] = __expf(sacc[nt][2] - mn1);
            sacc[nt][3] = __expf(sacc[nt][3] - mn1);
            sum0 += sacc[nt][0] + sacc[nt][1];
            sum1 += sacc[nt][2] + sacc[nt][3];
        }
        sum0 += __shfl_xor_sync(0xffffffffu, sum0, 1);
        sum0 += __shfl_xor_sync(0xffffffffu, sum0, 2);
        sum1 += __shfl_xor_sync(0xffffffffu, sum1, 1);
        sum1 += __shfl_xor_sync(0xffffffffu, sum1, 2);
        lrow0 = lrow0 * cr0 + sum0; mrow0 = mn0;
        lrow1 = lrow1 * cr1 + sum1; mrow1 = mn1;
        #pragma unroll
        for (int nt = 0; nt < 8; nt++) {
            oacc[nt][0] *= cr0; oacc[nt][1] *= cr0;
            oacc[nt][2] *= cr1; oacc[nt][3] *= cr1;
        }
        /* P -> per-warp smem region (tf32-rounded) */
        const int pr0 = w * 16 + g;
        #pragma unroll
        for (int nt = 0; nt < 8; nt++) {
            *(float2*)&Ps[ pr0      * FP + nt * 8 + 2 * t] =
                make_float2(tf32r(sacc[nt][0]), tf32r(sacc[nt][1]));
            *(float2*)&Ps[(pr0 + 8) * FP + nt * 8 + 2 * t] =
                make_float2(tf32r(sacc[nt][2]), tf32r(sacc[nt][3]));
        }
        __syncwarp();
        /* O += P V */
        #pragma unroll
        for (int ks = 0; ks < 8; ks++) {
            uint32_t af[4];
            af[0] = __float_as_uint(Ps[ pr0      * FP + ks * 8 + t    ]);
            af[1] = __float_as_uint(Ps[(pr0 + 8) * FP + ks * 8 + t    ]);
            af[2] = __float_as_uint(Ps[ pr0      * FP + ks * 8 + t + 4]);
            af[3] = __float_as_uint(Ps[(pr0 + 8) * FP + ks * 8 + t + 4]);
            #pragma unroll
            for (int nt = 0; nt < 8; nt++) {
                int c = nt * 8 + g;
                int sw = ((c >> 4) & 3) << 3;
                uint32_t bf[2];
                bf[0] = __float_as_uint(Vt[c * FP + ((ks * 8 + t    ) ^ sw)]);
                bf[1] = __float_as_uint(Vt[c * FP + ((ks * 8 + t + 4) ^ sw)]);
                mma_tf32(oacc[nt], af, bf);
            }
        }
        __syncthreads();      /* Ks/Vt reads done before next-iter overwrite */
    }
    /* epilogue: normalize, tf32-round (feeds wo GEMM), store */
    float inv0 = 1.f / lrow0, inv1 = 1.f / lrow1;
    float* ob = O + (size_t)(b * SS + qt * FBM) * DD + h * DKK;
    int r0 = w * 16 + g;
    #pragma unroll
    for (int nt = 0; nt < 8; nt++) {
        int col = nt * 8 + 2 * t;
        *(float2*)(ob + (size_t)r0 * DD + col) =
            make_float2(tf32r(oacc[nt][0] * inv0), tf32r(oacc[nt][1] * inv0));
        *(float2*)(ob + (size_t)(r0 + 8) * DD + col) =
            make_float2(tf32r(oacc[nt][2] * inv1), tf32r(oacc[nt][3] * inv1));
    }
}

/* ---------------- host orchestration (graph-capturable) ------------------- */
extern "C" void kernel_launch(void* const* d_in, const int* in_sizes, int n_in,
                              void* d_out, int out_size) {
    (void)in_sizes; (void)n_in; (void)out_size;
    const float* x    = (const float*)d_in[0];
    const int*   mask = (const int*)  d_in[1];
    const float* wq   = (const float*)d_in[2];
    const float* bq   = (const float*)d_in[3];
    const float* wk   = (const float*)d_in[4];
    const float* bk   = (const float*)d_in[5];
    const float* wv   = (const float*)d_in[6];
    const float* bv   = (const float*)d_in[7];
    const float* wo   = (const float*)d_in[8];
    const float* bo   = (const float*)d_in[9];
    const float* w1   = (const float*)d_in[10];
    const float* b1   = (const float*)d_in[11];
    const float* w2   = (const float*)d_in[12];
    const float* b2   = (const float*)d_in[13];
    const float* a1   = (const float*)d_in[14];
    const float* c1   = (const float*)d_in[15];
    const float* a2   = (const float*)d_in[16];
    const float* c2   = (const float*)d_in[17];
    float* out = (float*)d_out;

    float *ln1, *q, *k, *v, *attn, *h, *ln2, *ffn;
    float *wqc, *wkc, *wvc, *woc, *w1c, *w2c;
    cudaGetSymbolAddress((void**)&ln1,  g_ln1);
    cudaGetSymbolAddress((void**)&q,    g_q);
    cudaGetSymbolAddress((void**)&k,    g_k);
    cudaGetSymbolAddress((void**)&v,    g_v);
    cudaGetSymbolAddress((void**)&attn, g_attn);
    cudaGetSymbolAddress((void**)&h,    g_h);
    cudaGetSymbolAddress((void**)&ln2,  g_ln2);
    cudaGetSymbolAddress((void**)&ffn,  g_ffn);
    cudaGetSymbolAddress((void**)&wqc,  g_wqc);
    cudaGetSymbolAddress((void**)&wkc,  g_wkc);
    cudaGetSymbolAddress((void**)&wvc,  g_wvc);
    cudaGetSymbolAddress((void**)&woc,  g_woc);
    cudaGetSymbolAddress((void**)&w1c,  g_w1c);
    cudaGetSymbolAddress((void**)&w2c,  g_w2c);

    cudaFuncSetAttribute(flash_tc,
                         cudaFuncAttributeMaxDynamicSharedMemorySize, FSMEM);

    /* weight tf32 pre-rounding */
    cvt_tf32_kernel<<<(DD*DD/4)/256,   256>>>(wq, wqc, DD*DD/4);
    cvt_tf32_kernel<<<(DD*DD/4)/256,   256>>>(wk, wkc, DD*DD/4);
    cvt_tf32_kernel<<<(DD*DD/4)/256,   256>>>(wv, wvc, DD*DD/4);
    cvt_tf32_kernel<<<(DD*DD/4)/256,   256>>>(wo, woc, DD*DD/4);
    cvt_tf32_kernel<<<(DFFN*DD/4)/256, 256>>>(w1, w1c, DFFN*DD/4);
    cvt_tf32_kernel<<<(DFFN*DD/4)/256, 256>>>(w2, w2c, DFFN*DD/4);

    /* LN1 (tf32-rounded output) */
    ln_kernel<<<NTOK, 256>>>(x, a1, c1, ln1);
    /* Q,K,V projections (tf32-rounded output -> flash) */
    dim3 gq(DD / TBN, NTOK / TBM);
    gemm_tc<false,false,true><<<gq, 256>>>(ln1, wqc, bq, nullptr, q, NTOK, DD, DD);
    gemm_tc<false,false,true><<<gq, 256>>>(ln1, wkc, bk, nullptr, k, NTOK, DD, DD);
    gemm_tc<false,false,true><<<gq, 256>>>(ln1, wvc, bv, nullptr, v, NTOK, DD, DD);
    /* attention (tf32-rounded output -> wo GEMM) */
    flash_tc<<<dim3(SS / FBM, HH, BB), 256, FSMEM>>>(q, k, v, mask, attn);
    /* h = x + attn @ wo^T + bo  (fp32 output) */
    gemm_tc<false,true,false><<<gq, 256>>>(attn, woc, bo, x, h, NTOK, DD, DD);
    /* LN2 (tf32-rounded output) */
    ln_kernel<<<NTOK, 256>>>(h, a2, c2, ln2);
    /* ffn = relu(ln2 @ w1^T + b1)  (tf32-rounded output -> w2 GEMM) */
    gemm_tc<true,false,true><<<dim3(DFFN / TBN, NTOK / TBM), 256>>>(
        ln2, w1c, b1, nullptr, ffn, NTOK, DFFN, DD);
    /* out = h + ffn @ w2^T + b2  (fp32 output) */
    gemm_tc<false,true,false><<<gq, 256>>>(ffn, w2c, b2, h, out, NTOK, DD, DFFN);
}

// round 7
// speedup vs baseline: 3.5828x; 1.2075x over previous
#include <cuda_runtime.h>
#include <math.h>
#include <stdint.h>

#define BB   4
#define SS   2048
#define DD   1024
#define HH   16
#define DKK  64
#define DFFN 4096
#define NTOK (BB*SS)
#define LNEPS 1e-6f

/* ---------------- scratch (alloc-free: __device__ globals) ---------------- */
__device__ float g_ln1 [NTOK*DD];
__device__ float g_q   [NTOK*DD];
__device__ float g_k   [NTOK*DD];
__device__ float g_v   [NTOK*DD];
__device__ float g_attn[NTOK*DD];
__device__ float g_h   [NTOK*DD];
__device__ float g_ln2 [NTOK*DD];
__device__ float g_ffn [(size_t)NTOK*DFFN];
__device__ float g_wqc[DD*DD];
__device__ float g_wkc[DD*DD];
__device__ float g_wvc[DD*DD];
__device__ float g_woc[DD*DD];
__device__ float g_w1c[DFFN*DD];
__device__ float g_w2c[DD*DFFN];

/* ---------------- helpers ------------------------------------------------- */
__device__ __forceinline__ uint32_t f2tf32(float f) {
    uint32_t u;
    asm("cvt.rna.tf32.f32 %0, %1;" : "=r"(u) : "f"(f));
    return u;
}
__device__ __forceinline__ float tf32r(float f) {
    return __uint_as_float(f2tf32(f));
}
__device__ __forceinline__ void mma_tf32(float* c, const uint32_t* a, const uint32_t* b) {
    asm volatile(
        "mma.sync.aligned.m16n8k8.row.col.f32.tf32.tf32.f32 "
        "{%0,%1,%2,%3}, {%4,%5,%6,%7}, {%8,%9}, {%0,%1,%2,%3};"
        : "+f"(c[0]), "+f"(c[1]), "+f"(c[2]), "+f"(c[3])
        : "r"(a[0]), "r"(a[1]), "r"(a[2]), "r"(a[3]), "r"(b[0]), "r"(b[1]));
}
__device__ __forceinline__ void cp16s(uint32_t saddr, const void* g) {
    asm volatile("cp.async.cg.shared.global [%0], [%1], 16;" :: "r"(saddr), "l"(g));
}
__device__ __forceinline__ uint32_t smem_u32(const void* p) {
    return (uint32_t)__cvta_generic_to_shared(p);
}
__device__ __forceinline__ void ldsm4(uint32_t* r, uint32_t addr) {
    asm volatile("ldmatrix.sync.aligned.m8n8.x4.shared.b16 {%0,%1,%2,%3}, [%4];"
        : "=r"(r[0]), "=r"(r[1]), "=r"(r[2]), "=r"(r[3]) : "r"(addr));
}

/* ---------------- weight pre-rounding ------------------------------------- */
__global__ void cvt_tf32_kernel(const float* __restrict__ src,
                                float* __restrict__ dst, int n4) {
    int i = blockIdx.x * 256 + threadIdx.x;
    if (i < n4) {
        float4 v = ((const float4*)src)[i];
        float4 o;
        o.x = tf32r(v.x); o.y = tf32r(v.y); o.z = tf32r(v.z); o.w = tf32r(v.w);
        ((float4*)dst)[i] = o;
    }
}

/* ---------------- LayerNorm (tf32-rounded output) -------------------------- */
__global__ void ln_kernel(const float* __restrict__ x,
                          const float* __restrict__ ap,
                          const float* __restrict__ cp,
                          float* __restrict__ y) {
    __shared__ float sred[16];
    int row = blockIdx.x;
    int tid = threadIdx.x;
    const float4 v = ((const float4*)(x + (size_t)row*DD))[tid];
    float s  = v.x + v.y + v.z + v.w;
    float sq = v.x*v.x + v.y*v.y + v.z*v.z + v.w*v.w;
    #pragma unroll
    for (int off = 16; off > 0; off >>= 1) {
        s  += __shfl_xor_sync(0xffffffffu, s,  off);
        sq += __shfl_xor_sync(0xffffffffu, sq, off);
    }
    int warp = tid >> 5, lane = tid & 31;
    if (lane == 0) { sred[warp] = s; sred[warp + 8] = sq; }
    __syncthreads();
    float st = 0.f, sqt = 0.f;
    #pragma unroll
    for (int i = 0; i < 8; i++) { st += sred[i]; sqt += sred[i + 8]; }
    float mean = st * (1.0f / DD);
    float var  = (sqt - (float)DD * mean * mean) * (1.0f / (DD - 1));
    float stdv = sqrtf(fmaxf(var, 0.f));
    float inv  = ap[0] / (stdv + LNEPS);
    float beta = cp[0];
    float4 o;
    o.x = tf32r((v.x - mean) * inv + beta);
    o.y = tf32r((v.y - mean) * inv + beta);
    o.z = tf32r((v.z - mean) * inv + beta);
    o.w = tf32r((v.w - mean) * inv + beta);
    ((float4*)(y + (size_t)row*DD))[tid] = o;
}

/* ========== TF32 TC NT GEMM v2: 128x256 CTA, ldmatrix, SW128, cp.async ===== */
/* C = A[M,K] B[N,K]^T + bias (+relu)(+res). A,B pre-rounded tf32.            */
/* smem: 128B rows (TBK=32 floats), XOR-swizzled; 8 warps in 2(m)x4(n),       */
/* warp tile 64x64 (4 m16-tiles x 8 n8-tiles).                                */
#define TBM 128
#define TBN 256
#define TBK 32
#define A_STG 16384            /* 128 rows * 128B */
#define B_STG 32768            /* 256 rows * 128B */
#define GSMEM (2 * (A_STG + B_STG))   /* 96 KB */

template<bool RELU, bool RES, bool TFOUT>
__global__ void __launch_bounds__(256)
gemm_tc(const float* __restrict__ A, const float* __restrict__ Bw,
        const float* __restrict__ bias, const float* __restrict__ res,
        float* __restrict__ C, int M, int N, int K) {
    extern __shared__ __align__(1024) float sm[];
    const int tid = threadIdx.x;
    const int warp = tid >> 5, lane = tid & 31;
    const int g = lane >> 2, t = lane & 3;
    const int wm = warp & 1, wn = warp >> 1;
    const int bm = blockIdx.y, bn = blockIdx.x;

    const uint32_t smbase = smem_u32(sm);
    const uint32_t aoff[2] = { smbase,               smbase + A_STG };
    const uint32_t boff[2] = { smbase + 2 * A_STG,   smbase + 2 * A_STG + B_STG };

    const float* Ab = A  + (size_t)(bm * TBM) * K;
    const float* Bb = Bw + (size_t)(bn * TBN) * K;
    const int ntiles = K / TBK;

    float acc[4][8][4] = {};

    /* ldmatrix per-thread address components */
    const int aR = lane & 15;                       /* row offset in m16 tile  */
    const int aH = lane >> 4;                       /* k-chunk half (0/1)      */
    const int bR = ((lane >> 4) << 3) + (lane & 7); /* row offset in n16 pair  */
    const int bH = (lane >> 3) & 1;                 /* k-chunk half (0/1)      */
    const int lx = lane & 7;                        /* swizzle xor = row&7     */

    /* stage k-tile k0 into buffer buf */
    #define STAGE(buf, k0)                                                     \
    {                                                                          \
        _Pragma("unroll")                                                      \
        for (int i = 0; i < 4; i++) {                                          \
            int s = tid + i * 256;                                             \
            int r = s >> 3, c = s & 7;                                         \
            cp16s(aoff[buf] + r * 128 + (((c ^ (r & 7)) << 4)),                \
                  Ab + (size_t)r * K + (k0) + c * 4);                          \
        }                                                                      \
        _Pragma("unroll")                                                      \
        for (int i = 0; i < 8; i++) {                                          \
            int s = tid + i * 256;                                             \
            int r = s >> 3, c = s & 7;                                         \
            cp16s(boff[buf] + r * 128 + (((c ^ (r & 7)) << 4)),                \
                  Bb + (size_t)r * K + (k0) + c * 4);                          \
        }                                                                      \
    }

    STAGE(0, 0);
    asm volatile("cp.async.commit_group;");

    for (int kt = 0; kt < ntiles; kt++) {
        if (kt + 1 < ntiles) {
            STAGE((kt + 1) & 1, (kt + 1) * TBK);
            asm volatile("cp.async.commit_group;");
            asm volatile("cp.async.wait_group 1;");
        } else {
            asm volatile("cp.async.commit_group;");
            asm volatile("cp.async.wait_group 0;");
        }
        __syncthreads();
        const uint32_t ab = aoff[kt & 1], bb = boff[kt & 1];
        #pragma unroll
        for (int ks4 = 0; ks4 < 8; ks4 += 2) {      /* ks4 = (k8-step)*2 */
            uint32_t af[4][4], bf[4][4];
            #pragma unroll
            for (int mt = 0; mt < 4; mt++) {
                int R = wm * 64 + mt * 16 + aR;
                ldsm4(af[mt], ab + R * 128 + ((((ks4 + aH) ^ lx)) << 4));
            }
            #pragma unroll
            for (int jp = 0; jp < 4; jp++) {
                int R = wn * 64 + jp * 16 + bR;
                ldsm4(bf[jp], bb + R * 128 + ((((ks4 + bH) ^ lx)) << 4));
            }
            #pragma unroll
            for (int mt = 0; mt < 4; mt++)
                #pragma unroll
                for (int nt = 0; nt < 8; nt++)
                    mma_tf32(acc[mt][nt], af[mt], &bf[nt >> 1][(nt & 1) * 2]);
        }
        __syncthreads();
    }
    #undef STAGE

    /* epilogue */
    #pragma unroll
    for (int mt = 0; mt < 4; mt++) {
        #pragma unroll
        for (int nt = 0; nt < 8; nt++) {
            int col = bn * TBN + wn * 64 + nt * 8 + t * 2;
            float bx = bias[col], by = bias[col + 1];
            #pragma unroll
            for (int half = 0; half < 2; half++) {
                size_t row = (size_t)(bm * TBM + wm * 64 + mt * 16 + g + half * 8);
                float ox = acc[mt][nt][half * 2 + 0] + bx;
                float oy = acc[mt][nt][half * 2 + 1] + by;
                if (RELU) { ox = fmaxf(ox, 0.f); oy = fmaxf(oy, 0.f); }
                if (TFOUT) { ox = tf32r(ox); oy = tf32r(oy); }
                if (RES) {
                    float2 r2 = *(const float2*)(res + row * N + col);
                    ox += r2.x; oy += r2.y;
                }
                *(float2*)(C + row * N + col) = make_float2(ox, oy);
            }
        }
    }
}

/* ---------------- TF32 flash attention (unchanged from R5) ---------------- */
#define FBM 128
#define FBN 64
#define FP  68
#define FNT (SS / FBN)
#define FSMEM ((FBM + 2 * FBN) * FP * 4)

__global__ void __launch_bounds__(256, 1)
flash_tc(const float* __restrict__ Q, const float* __restrict__ Kg,
         const float* __restrict__ Vg, const int* __restrict__ mask,
         float* __restrict__ O) {
    extern __shared__ float fs[];
    float* Qs = fs;
    float* Ks = fs + FBM * FP;
    float* Vt = fs + (FBM + FBN) * FP;

    const int qt = blockIdx.x, h = blockIdx.y, b = blockIdx.z;
    const int tid = threadIdx.x;
    const int w = tid >> 5, lane = tid & 31, g = lane >> 2, t = lane & 3;

    const float* qb = Q + (size_t)(b * SS + qt * FBM) * DD + h * DKK;
    #pragma unroll
    for (int it = 0; it < 8; it++) {
        int lin = tid + it * 256;
        int r = lin >> 4, cg = (lin & 15) * 4;
        *(float4*)&Qs[r * FP + cg] = *(const float4*)(qb + (size_t)r * DD + cg);
    }
    __syncthreads();
    uint32_t qf[8][4];
    {
        int r0 = w * 16 + g;
        #pragma unroll
        for (int ks = 0; ks < 8; ks++) {
            qf[ks][0] = __float_as_uint(Qs[ r0      * FP + ks * 8 + t    ]);
            qf[ks][1] = __float_as_uint(Qs[(r0 + 8) * FP + ks * 8 + t    ]);
            qf[ks][2] = __float_as_uint(Qs[ r0      * FP + ks * 8 + t + 4]);
            qf[ks][3] = __float_as_uint(Qs[(r0 + 8) * FP + ks * 8 + t + 4]);
        }
    }
    __syncthreads();
    float* Ps = Qs;

    float oacc[8][4] = {};
    float mrow0 = -1e30f, mrow1 = -1e30f, lrow0 = 0.f, lrow1 = 0.f;

    const int kr = tid >> 2;
    const int kc = (tid & 3) * 16;
    const float* kb = Kg + (size_t)(b * SS) * DD + h * DKK;
    const float* vb = Vg + (size_t)(b * SS) * DD + h * DKK;
    float4 kpre[4], vpre[4];
    #pragma unroll
    for (int j = 0; j < 4; j++) {
        kpre[j] = *(const float4*)(kb + (size_t)kr * DD + kc + j * 4);
        vpre[j] = *(const float4*)(vb + (size_t)kr * DD + kc + j * 4);
    }
    const int* mp = mask + b * SS;

    for (int kt = 0; kt < FNT; kt++) {
        #pragma unroll
        for (int j = 0; j < 4; j++)
            *(float4*)&Ks[kr * FP + kc + j * 4] = kpre[j];
        #pragma unroll
        for (int j = 0; j < 4; j++) {
            int c = kc + j * 4;
            Vt[(c+0) * FP + (kr ^ ((((c+0) >> 4) & 3) << 3))] = vpre[j].x;
            Vt[(c+1) * FP + (kr ^ ((((c+1) >> 4) & 3) << 3))] = vpre[j].y;
            Vt[(c+2) * FP + (kr ^ ((((c+2) >> 4) & 3) << 3))] = vpre[j].z;
            Vt[(c+3) * FP + (kr ^ ((((c+3) >> 4) & 3) << 3))] = vpre[j].w;
        }
        __syncthreads();
        if (kt + 1 < FNT) {
            const float* kn = kb + (size_t)((kt + 1) * FBN + kr) * DD + kc;
            const float* vn = vb + (size_t)((kt + 1) * FBN + kr) * DD + kc;
            #pragma unroll
            for (int j = 0; j < 4; j++) {
                kpre[j] = *(const float4*)(kn + j * 4);
                vpre[j] = *(const float4*)(vn + j * 4);
            }
        }
        int mk0[8], mk1[8];
        #pragma unroll
        for (int nt = 0; nt < 8; nt++) {
            mk0[nt] = __ldg(mp + kt * FBN + nt * 8 + 2 * t);
            mk1[nt] = __ldg(mp + kt * FBN + nt * 8 + 2 * t + 1);
        }
        float sacc[8][4] = {};
        #pragma unroll
        for (int ks = 0; ks < 8; ks++) {
            #pragma unroll
            for (int nt = 0; nt < 8; nt++) {
                uint32_t bf[2];
                bf[0] = __float_as_uint(Ks[(nt * 8 + g) * FP + ks * 8 + t    ]);
                bf[1] = __float_as_uint(Ks[(nt * 8 + g) * FP + ks * 8 + t + 4]);
                mma_tf32(sacc[nt], qf[ks], bf);
            }
        }
        #pragma unroll
        for (int nt = 0; nt < 8; nt++) {
            sacc[nt][0] = mk0[nt] ? sacc[nt][0] * 0.125f : -1e9f;
            sacc[nt][1] = mk1[nt] ? sacc[nt][1] * 0.125f : -1e9f;
            sacc[nt][2] = mk0[nt] ? sacc[nt][2] * 0.125f : -1e9f;
            sacc[nt][3] = mk1[nt] ? sacc[nt][3] * 0.125f : -1e9f;
        }
        float tm0 = -1e30f, tm1 = -1e30f;
        #pragma unroll
        for (int nt = 0; nt < 8; nt++) {
            tm0 = fmaxf(tm0, fmaxf(sacc[nt][0], sacc[nt][1]));
            tm1 = fmaxf(tm1, fmaxf(sacc[nt][2], sacc[nt][3]));
        }
        tm0 = fmaxf(tm0, __shfl_xor_sync(0xffffffffu, tm0, 1));
        tm0 = fmaxf(tm0, __shfl_xor_sync(0xffffffffu, tm0, 2));
        tm1 = fmaxf(tm1, __shfl_xor_sync(0xffffffffu, tm1, 1));
        tm1 = fmaxf(tm1, __shfl_xor_sync(0xffffffffu, tm1, 2));
        float mn0 = fmaxf(mrow0, tm0), mn1 = fmaxf(mrow1, tm1);
        float cr0 = __expf(mrow0 - mn0), cr1 = __expf(mrow1 - mn1);
        float sum0 = 0.f, sum1 = 0.f;
        #pragma unroll
        for (int nt = 0; nt < 8; nt++) {
            sacc[nt][0] = __expf(sacc[nt][0] - mn0);
            sacc[nt][1] = __expf(sacc[nt][1] - mn0);
            sacc[nt][2] = __expf(sacc[nt][2] - mn1);
            sacc[nt][3] = __expf(sacc[nt][3] - mn1);
            sum0 += sacc[nt][0] + sacc[nt][1];
            sum1 += sacc[nt][2] + sacc[nt][3];
        }
        sum0 += __shfl_xor_sync(0xffffffffu, sum0, 1);
        sum0 += __shfl_xor_sync(0xffffffffu, sum0, 2);
        sum1 += __shfl_xor_sync(0xffffffffu, sum1, 1);
        sum1 += __shfl_xor_sync(0xffffffffu, sum1, 2);
        lrow0 = lrow0 * cr0 + sum0; mrow0 = mn0;
        lrow1 = lrow1 * cr1 + sum1; mrow1 = mn1;
        #pragma unroll
        for (int nt = 0; nt < 8; nt++) {
            oacc[nt][0] *= cr0; oacc[nt][1] *= cr0;
            oacc[nt][2] *= cr1; oacc[nt][3] *= cr1;
        }
        const int pr0 = w * 16 + g;
        #pragma unroll
        for (int nt = 0; nt < 8; nt++) {
            *(float2*)&Ps[ pr0      * FP + nt * 8 + 2 * t] =
                make_float2(tf32r(sacc[nt][0]), tf32r(sacc[nt][1]));
            *(float2*)&Ps[(pr0 + 8) * FP + nt * 8 + 2 * t] =
                make_float2(tf32r(sacc[nt][2]), tf32r(sacc[nt][3]));
        }
        __syncwarp();
        #pragma unroll
        for (int ks = 0; ks < 8; ks++) {
            uint32_t af[4];
            af[0] = __float_as_uint(Ps[ pr0      * FP + ks * 8 + t    ]);
            af[1] = __float_as_uint(Ps[(pr0 + 8) * FP + ks * 8 + t    ]);
            af[2] = __float_as_uint(Ps[ pr0      * FP + ks * 8 + t + 4]);
            af[3] = __float_as_uint(Ps[(pr0 + 8) * FP + ks * 8 + t + 4]);
            #pragma unroll
            for (int nt = 0; nt < 8; nt++) {
                int c = nt * 8 + g;
                int sw = ((c >> 4) & 3) << 3;
                uint32_t bf[2];
                bf[0] = __float_as_uint(Vt[c * FP + ((ks * 8 + t    ) ^ sw)]);
                bf[1] = __float_as_uint(Vt[c * FP + ((ks * 8 + t + 4) ^ sw)]);
                mma_tf32(oacc[nt], af, bf);
            }
        }
        __syncthreads();
    }
    float inv0 = 1.f / lrow0, inv1 = 1.f / lrow1;
    float* ob = O + (size_t)(b * SS + qt * FBM) * DD + h * DKK;
    int r0 = w * 16 + g;
    #pragma unroll
    for (int nt = 0; nt < 8; nt++) {
        int col = nt * 8 + 2 * t;
        *(float2*)(ob + (size_t)r0 * DD + col) =
            make_float2(tf32r(oacc[nt][0] * inv0), tf32r(oacc[nt][1] * inv0));
        *(float2*)(ob + (size_t)(r0 + 8) * DD + col) =
            make_float2(tf32r(oacc[nt][2] * inv1), tf32r(oacc[nt][3] * inv1));
    }
}

/* ---------------- host orchestration (graph-capturable) ------------------- */
extern "C" void kernel_launch(void* const* d_in, const int* in_sizes, int n_in,
                              void* d_out, int out_size) {
    (void)in_sizes; (void)n_in; (void)out_size;
    const float* x    = (const float*)d_in[0];
    const int*   mask = (const int*)  d_in[1];
    const float* wq   = (const float*)d_in[2];
    const float* bq   = (const float*)d_in[3];
    const float* wk   = (const float*)d_in[4];
    const float* bk   = (const float*)d_in[5];
    const float* wv   = (const float*)d_in[6];
    const float* bv   = (const float*)d_in[7];
    const float* wo   = (const float*)d_in[8];
    const float* bo   = (const float*)d_in[9];
    const float* w1   = (const float*)d_in[10];
    const float* b1   = (const float*)d_in[11];
    const float* w2   = (const float*)d_in[12];
    const float* b2   = (const float*)d_in[13];
    const float* a1   = (const float*)d_in[14];
    const float* c1   = (const float*)d_in[15];
    const float* a2   = (const float*)d_in[16];
    const float* c2   = (const float*)d_in[17];
    float* out = (float*)d_out;

    float *ln1, *q, *k, *v, *attn, *h, *ln2, *ffn;
    float *wqc, *wkc, *wvc, *woc, *w1c, *w2c;
    cudaGetSymbolAddress((void**)&ln1,  g_ln1);
    cudaGetSymbolAddress((void**)&q,    g_q);
    cudaGetSymbolAddress((void**)&k,    g_k);
    cudaGetSymbolAddress((void**)&v,    g_v);
    cudaGetSymbolAddress((void**)&attn, g_attn);
    cudaGetSymbolAddress((void**)&h,    g_h);
    cudaGetSymbolAddress((void**)&ln2,  g_ln2);
    cudaGetSymbolAddress((void**)&ffn,  g_ffn);
    cudaGetSymbolAddress((void**)&wqc,  g_wqc);
    cudaGetSymbolAddress((void**)&wkc,  g_wkc);
    cudaGetSymbolAddress((void**)&wvc,  g_wvc);
    cudaGetSymbolAddress((void**)&woc,  g_woc);
    cudaGetSymbolAddress((void**)&w1c,  g_w1c);
    cudaGetSymbolAddress((void**)&w2c,  g_w2c);

    cudaFuncSetAttribute(flash_tc,
                         cudaFuncAttributeMaxDynamicSharedMemorySize, FSMEM);
    cudaFuncSetAttribute(gemm_tc<false,false,true>,
                         cudaFuncAttributeMaxDynamicSharedMemorySize, GSMEM);
    cudaFuncSetAttribute(gemm_tc<false,true,false>,
                         cudaFuncAttributeMaxDynamicSharedMemorySize, GSMEM);
    cudaFuncSetAttribute(gemm_tc<true,false,true>,
                         cudaFuncAttributeMaxDynamicSharedMemorySize, GSMEM);

    /* weight tf32 pre-rounding */
    cvt_tf32_kernel<<<(DD*DD/4)/256,   256>>>(wq, wqc, DD*DD/4);
    cvt_tf32_kernel<<<(DD*DD/4)/256,   256>>>(wk, wkc, DD*DD/4);
    cvt_tf32_kernel<<<(DD*DD/4)/256,   256>>>(wv, wvc, DD*DD/4);
    cvt_tf32_kernel<<<(DD*DD/4)/256,   256>>>(wo, woc, DD*DD/4);
    cvt_tf32_kernel<<<(DFFN*DD/4)/256, 256>>>(w1, w1c, DFFN*DD/4);
    cvt_tf32_kernel<<<(DFFN*DD/4)/256, 256>>>(w2, w2c, DFFN*DD/4);

    /* LN1 */
    ln_kernel<<<NTOK, 256>>>(x, a1, c1, ln1);
    /* Q,K,V projections */
    dim3 gq(DD / TBN, NTOK / TBM);
    gemm_tc<false,false,true><<<gq, 256, GSMEM>>>(ln1, wqc, bq, nullptr, q, NTOK, DD, DD);
    gemm_tc<false,false,true><<<gq, 256, GSMEM>>>(ln1, wkc, bk, nullptr, k, NTOK, DD, DD);
    gemm_tc<false,false,true><<<gq, 256, GSMEM>>>(ln1, wvc, bv, nullptr, v, NTOK, DD, DD);
    /* attention */
    flash_tc<<<dim3(SS / FBM, HH, BB), 256, FSMEM>>>(q, k, v, mask, attn);
    /* h = x + attn @ wo^T + bo */
    gemm_tc<false,true,false><<<gq, 256, GSMEM>>>(attn, woc, bo, x, h, NTOK, DD, DD);
    /* LN2 */
    ln_kernel<<<NTOK, 256>>>(h, a2, c2, ln2);
    /* ffn = relu(ln2 @ w1^T + b1) */
    gemm_tc<true,false,true><<<dim3(DFFN / TBN, NTOK / TBM), 256, GSMEM>>>(
        ln2, w1c, b1, nullptr, ffn, NTOK, DFFN, DD);
    /* out = h + ffn @ w2^T + b2 */
    gemm_tc<false,true,false><<<gq, 256, GSMEM>>>(ffn, w2c, b2, h, out, NTOK, DD, DFFN);
}

// round 9
// speedup vs baseline: 4.4453x; 1.2407x over previous
#include <cuda_runtime.h>
#include <cuda_bf16.h>
#include <math.h>
#include <stdint.h>

#define BB   4
#define SS   2048
#define DD   1024
#define HH   16
#define DKK  64
#define DFFN 4096
#define NTOK (BB*SS)
#define LNEPS 1e-6f

/* ---------------- scratch (alloc-free: __device__ globals) ---------------- */
__device__ float g_ln1 [NTOK*DD];
__device__ __nv_bfloat16 g_qb[NTOK*DD];
__device__ __nv_bfloat16 g_kb[NTOK*DD];
__device__ __nv_bfloat16 g_vb[NTOK*DD];
__device__ float g_attn[NTOK*DD];
__device__ float g_h   [NTOK*DD];
__device__ float g_ln2 [NTOK*DD];
__device__ float g_ffn [(size_t)NTOK*DFFN];
__device__ float g_wqc[DD*DD];
__device__ float g_wkc[DD*DD];
__device__ float g_wvc[DD*DD];
__device__ float g_woc[DD*DD];
__device__ float g_w1c[DFFN*DD];
__device__ float g_w2c[DD*DFFN];

/* ---------------- helpers ------------------------------------------------- */
__device__ __forceinline__ uint32_t f2tf32(float f) {
    uint32_t u;
    asm("cvt.rna.tf32.f32 %0, %1;" : "=r"(u) : "f"(f));
    return u;
}
__device__ __forceinline__ float tf32r(float f) {
    return __uint_as_float(f2tf32(f));
}
__device__ __forceinline__ uint32_t pack_bf16(float lo, float hi) {
    uint32_t r;
    asm("cvt.rn.bf16x2.f32 %0, %1, %2;" : "=r"(r) : "f"(hi), "f"(lo));
    return r;
}
__device__ __forceinline__ void mma_tf32(float* c, const uint32_t* a, const uint32_t* b) {
    asm volatile(
        "mma.sync.aligned.m16n8k8.row.col.f32.tf32.tf32.f32 "
        "{%0,%1,%2,%3}, {%4,%5,%6,%7}, {%8,%9}, {%0,%1,%2,%3};"
        : "+f"(c[0]), "+f"(c[1]), "+f"(c[2]), "+f"(c[3])
        : "r"(a[0]), "r"(a[1]), "r"(a[2]), "r"(a[3]), "r"(b[0]), "r"(b[1]));
}
__device__ __forceinline__ void mma_bf16(float* c, const uint32_t* a, const uint32_t* b) {
    asm volatile(
        "mma.sync.aligned.m16n8k16.row.col.f32.bf16.bf16.f32 "
        "{%0,%1,%2,%3}, {%4,%5,%6,%7}, {%8,%9}, {%0,%1,%2,%3};"
        : "+f"(c[0]), "+f"(c[1]), "+f"(c[2]), "+f"(c[3])
        : "r"(a[0]), "r"(a[1]), "r"(a[2]), "r"(a[3]), "r"(b[0]), "r"(b[1]));
}
__device__ __forceinline__ void cp16s(uint32_t saddr, const void* g) {
    asm volatile("cp.async.cg.shared.global [%0], [%1], 16;" :: "r"(saddr), "l"(g));
}
__device__ __forceinline__ uint32_t smem_u32(const void* p) {
    return (uint32_t)__cvta_generic_to_shared(p);
}
__device__ __forceinline__ void ldsm4(uint32_t* r, uint32_t addr) {
    asm volatile("ldmatrix.sync.aligned.m8n8.x4.shared.b16 {%0,%1,%2,%3}, [%4];"
        : "=r"(r[0]), "=r"(r[1]), "=r"(r[2]), "=r"(r[3]) : "r"(addr));
}
__device__ __forceinline__ void ldsm4t(uint32_t* r, uint32_t addr) {
    asm volatile("ldmatrix.sync.aligned.m8n8.x4.trans.shared.b16 {%0,%1,%2,%3}, [%4];"
        : "=r"(r[0]), "=r"(r[1]), "=r"(r[2]), "=r"(r[3]) : "r"(addr));
}

/* ---------------- weight pre-rounding ------------------------------------- */
__global__ void cvt_tf32_kernel(const float* __restrict__ src,
                                float* __restrict__ dst, int n4) {
    int i = blockIdx.x * 256 + threadIdx.x;
    if (i < n4) {
        float4 v = ((const float4*)src)[i];
        float4 o;
        o.x = tf32r(v.x); o.y = tf32r(v.y); o.z = tf32r(v.z); o.w = tf32r(v.w);
        ((float4*)dst)[i] = o;
    }
}

/* ---------------- LayerNorm (tf32-rounded output) -------------------------- */
__global__ void ln_kernel(const float* __restrict__ x,
                          const float* __restrict__ ap,
                          const float* __restrict__ cp,
                          float* __restrict__ y) {
    __shared__ float sred[16];
    int row = blockIdx.x;
    int tid = threadIdx.x;
    const float4 v = ((const float4*)(x + (size_t)row*DD))[tid];
    float s  = v.x + v.y + v.z + v.w;
    float sq = v.x*v.x + v.y*v.y + v.z*v.z + v.w*v.w;
    #pragma unroll
    for (int off = 16; off > 0; off >>= 1) {
        s  += __shfl_xor_sync(0xffffffffu, s,  off);
        sq += __shfl_xor_sync(0xffffffffu, sq, off);
    }
    int warp = tid >> 5, lane = tid & 31;
    if (lane == 0) { sred[warp] = s; sred[warp + 8] = sq; }
    __syncthreads();
    float st = 0.f, sqt = 0.f;
    #pragma unroll
    for (int i = 0; i < 8; i++) { st += sred[i]; sqt += sred[i + 8]; }
    float mean = st * (1.0f / DD);
    float var  = (sqt - (float)DD * mean * mean) * (1.0f / (DD - 1));
    float stdv = sqrtf(fmaxf(var, 0.f));
    float inv  = ap[0] / (stdv + LNEPS);
    float beta = cp[0];
    float4 o;
    o.x = tf32r((v.x - mean) * inv + beta);
    o.y = tf32r((v.y - mean) * inv + beta);
    o.z = tf32r((v.z - mean) * inv + beta);
    o.w = tf32r((v.w - mean) * inv + beta);
    ((float4*)(y + (size_t)row*DD))[tid] = o;
}

/* ========== TF32 TC NT GEMM: 128x256 CTA, ldmatrix, SW128, cp.async ======== */
#define TBM 128
#define TBN 256
#define TBK 32
#define A_STG 16384
#define B_STG 32768
#define GSMEM (2 * (A_STG + B_STG))   /* 96 KB */

template<bool RELU, bool RES, bool TFOUT, bool BF16OUT>
__global__ void __launch_bounds__(256)
gemm_tc(const float* __restrict__ A, const float* __restrict__ Bw,
        const float* __restrict__ bias, const float* __restrict__ res,
        void* __restrict__ Cv, int M, int N, int K) {
    extern __shared__ __align__(1024) float sm[];
    const int tid = threadIdx.x;
    const int warp = tid >> 5, lane = tid & 31;
    const int g = lane >> 2, t = lane & 3;
    const int wm = warp & 1, wn = warp >> 1;
    const int bm = blockIdx.y, bn = blockIdx.x;

    const uint32_t smbase = smem_u32(sm);
    const uint32_t aoff[2] = { smbase,               smbase + A_STG };
    const uint32_t boff[2] = { smbase + 2 * A_STG,   smbase + 2 * A_STG + B_STG };

    const float* Ab = A  + (size_t)(bm * TBM) * K;
    const float* Bb = Bw + (size_t)(bn * TBN) * K;
    const int ntiles = K / TBK;

    float acc[4][8][4] = {};

    const int aR = lane & 15;
    const int aH = lane >> 4;
    const int bR = ((lane >> 4) << 3) + (lane & 7);
    const int bH = (lane >> 3) & 1;
    const int lx = lane & 7;

    #define STAGE(buf, k0)                                                     \
    {                                                                          \
        _Pragma("unroll")                                                      \
        for (int i = 0; i < 4; i++) {                                          \
            int s = tid + i * 256;                                             \
            int r = s >> 3, c = s & 7;                                         \
            cp16s(aoff[buf] + r * 128 + (((c ^ (r & 7)) << 4)),                \
                  Ab + (size_t)r * K + (k0) + c * 4);                          \
        }                                                                      \
        _Pragma("unroll")                                                      \
        for (int i = 0; i < 8; i++) {                                          \
            int s = tid + i * 256;                                             \
            int r = s >> 3, c = s & 7;                                         \
            cp16s(boff[buf] + r * 128 + (((c ^ (r & 7)) << 4)),                \
                  Bb + (size_t)r * K + (k0) + c * 4);                          \
        }                                                                      \
    }

    STAGE(0, 0);
    asm volatile("cp.async.commit_group;");

    for (int kt = 0; kt < ntiles; kt++) {
        if (kt + 1 < ntiles) {
            STAGE((kt + 1) & 1, (kt + 1) * TBK);
            asm volatile("cp.async.commit_group;");
            asm volatile("cp.async.wait_group 1;");
        } else {
            asm volatile("cp.async.commit_group;");
            asm volatile("cp.async.wait_group 0;");
        }
        __syncthreads();
        const uint32_t ab = aoff[kt & 1], bb = boff[kt & 1];
        #pragma unroll
        for (int ks4 = 0; ks4 < 8; ks4 += 2) {
            uint32_t af[4][4], bf[4][4];
            #pragma unroll
            for (int mt = 0; mt < 4; mt++) {
                int R = wm * 64 + mt * 16 + aR;
                ldsm4(af[mt], ab + R * 128 + ((((ks4 + aH) ^ lx)) << 4));
            }
            #pragma unroll
            for (int jp = 0; jp < 4; jp++) {
                int R = wn * 64 + jp * 16 + bR;
                ldsm4(bf[jp], bb + R * 128 + ((((ks4 + bH) ^ lx)) << 4));
            }
            #pragma unroll
            for (int mt = 0; mt < 4; mt++)
                #pragma unroll
                for (int nt = 0; nt < 8; nt++)
                    mma_tf32(acc[mt][nt], af[mt], &bf[nt >> 1][(nt & 1) * 2]);
        }
        __syncthreads();
    }
    #undef STAGE

    /* epilogue */
    #pragma unroll
    for (int mt = 0; mt < 4; mt++) {
        #pragma unroll
        for (int nt = 0; nt < 8; nt++) {
            int col = bn * TBN + wn * 64 + nt * 8 + t * 2;
            float bx = bias[col], by = bias[col + 1];
            #pragma unroll
            for (int half = 0; half < 2; half++) {
                size_t row = (size_t)(bm * TBM + wm * 64 + mt * 16 + g + half * 8);
                float ox = acc[mt][nt][half * 2 + 0] + bx;
                float oy = acc[mt][nt][half * 2 + 1] + by;
                if (RELU) { ox = fmaxf(ox, 0.f); oy = fmaxf(oy, 0.f); }
                if (TFOUT) { ox = tf32r(ox); oy = tf32r(oy); }
                if (RES) {
                    float2 r2 = *(const float2*)(res + row * N + col);
                    ox += r2.x; oy += r2.y;
                }
                if (BF16OUT) {
                    *(uint32_t*)((__nv_bfloat16*)Cv + row * N + col) = pack_bf16(ox, oy);
                } else {
                    *(float2*)((float*)Cv + row * N + col) = make_float2(ox, oy);
                }
            }
        }
    }
}

/* ================= bf16 flash attention =================================== */
#define FBM 128
#define FBN 64
#define FNT (SS / FBN)
#define FQP   0
#define FK    16384
#define FV    (16384 + 2 * 8192)
#define FSMEM (16384 + 4 * 8192)

__global__ void __launch_bounds__(256, 1)
flash_bf16(const __nv_bfloat16* __restrict__ Q,
           const __nv_bfloat16* __restrict__ Kg,
           const __nv_bfloat16* __restrict__ Vg,
           const int* __restrict__ mask, float* __restrict__ O) {
    extern __shared__ __align__(1024) char fsm[];
    const uint32_t sb = smem_u32(fsm);
    const uint32_t qp = sb + FQP;
    const uint32_t koff[2] = { sb + FK, sb + FK + 8192 };
    const uint32_t voff[2] = { sb + FV, sb + FV + 8192 };

    const int qt = blockIdx.x, h = blockIdx.y, b = blockIdx.z;
    const int tid = threadIdx.x;
    const int w = tid >> 5, lane = tid & 31, g = lane >> 2, t = lane & 3;

    /* ---- load Q tile into swizzled smem ---- */
    const __nv_bfloat16* qb = Q + (size_t)(b * SS + qt * FBM) * DD + h * DKK;
    #pragma unroll
    for (int i = 0; i < 4; i++) {
        int s = tid + i * 256;
        int r = s >> 3, c = s & 7;
        *(uint4*)(fsm + FQP + r * 128 + ((c ^ (r & 7)) << 4)) =
            *(const uint4*)(qb + (size_t)r * DD + c * 8);
    }
    __syncthreads();
    uint32_t qf[4][4];
    {
        const int R = w * 16 + (lane & 15);
        const int hh = lane >> 4;
        #pragma unroll
        for (int ks = 0; ks < 4; ks++)
            ldsm4(qf[ks], qp + R * 128 + (((ks * 2 + hh) ^ (R & 7)) << 4));
    }
    __syncthreads();   /* Q smem now free -> per-warp P region */

    const __nv_bfloat16* kb = Kg + (size_t)(b * SS) * DD + h * DKK;
    const __nv_bfloat16* vb = Vg + (size_t)(b * SS) * DD + h * DKK;
    #define KVSTAGE(buf, kt)                                                   \
    {                                                                          \
        const __nv_bfloat16* kg = kb + (size_t)((kt) * FBN) * DD;              \
        const __nv_bfloat16* vg = vb + (size_t)((kt) * FBN) * DD;              \
        _Pragma("unroll")                                                      \
        for (int i = 0; i < 2; i++) {                                          \
            int s = tid + i * 256;                                             \
            int r = s >> 3, c = s & 7;                                         \
            cp16s(koff[buf] + r * 128 + ((c ^ (r & 7)) << 4),                  \
                  kg + (size_t)r * DD + c * 8);                                \
            cp16s(voff[buf] + r * 128 + ((c ^ (r & 7)) << 4),                  \
                  vg + (size_t)r * DD + c * 8);                                \
        }                                                                      \
    }
    KVSTAGE(0, 0);
    asm volatile("cp.async.commit_group;");

    float oacc[8][4] = {};
    float mrow0 = -1e30f, mrow1 = -1e30f, lrow0 = 0.f, lrow1 = 0.f;
    const int* mp = mask + b * SS;

    /* ldmatrix address components */
    const int kbR = (lane & 7) + ((lane >> 4) << 3);   /* K (non-trans B): row, n dim   */
    const int kbH = (lane >> 3) & 1;                   /* K: k8-chunk select            */
    const int vbR = (lane & 7) + (((lane >> 3) & 1) << 3); /* V (trans B): row = k dim  */
    const int vbH = lane >> 4;                             /* V: n-chunk select         */
    const int paR = lane & 15, paH = lane >> 4;        /* P (A-frag): row / k-half      */

    for (int kt = 0; kt < FNT; kt++) {
        if (kt + 1 < FNT) {
            KVSTAGE((kt + 1) & 1, kt + 1);
            asm volatile("cp.async.commit_group;");
            asm volatile("cp.async.wait_group 1;");
        } else {
            asm volatile("cp.async.commit_group;");
            asm volatile("cp.async.wait_group 0;");
        }
        __syncthreads();
        const uint32_t kbuf = koff[kt & 1], vbuf = voff[kt & 1];

        /* ---- S = Q K^T ---- */
        float sacc[8][4] = {};
        #pragma unroll
        for (int ks = 0; ks < 4; ks++) {
            #pragma unroll
            for (int np = 0; np < 4; np++) {
                uint32_t bf[4];
                int R = np * 16 + kbR;
                ldsm4(bf, kbuf + R * 128 + (((ks * 2 + kbH) ^ (R & 7)) << 4));
                mma_bf16(sacc[np * 2 + 0], qf[ks], &bf[0]);
                mma_bf16(sacc[np * 2 + 1], qf[ks], &bf[2]);
            }
        }
        /* ---- scale + mask ---- */
        #pragma unroll
        for (int nt = 0; nt < 8; nt++) {
            int mj0 = __ldg(mp + kt * FBN + nt * 8 + 2 * t);
            int mj1 = __ldg(mp + kt * FBN + nt * 8 + 2 * t + 1);
            sacc[nt][0] = mj0 ? sacc[nt][0] * 0.125f : -1e9f;
            sacc[nt][1] = mj1 ? sacc[nt][1] * 0.125f : -1e9f;
            sacc[nt][2] = mj0 ? sacc[nt][2] * 0.125f : -1e9f;
            sacc[nt][3] = mj1 ? sacc[nt][3] * 0.125f : -1e9f;
        }
        /* ---- online softmax ---- */
        float tm0 = -1e30f, tm1 = -1e30f;
        #pragma unroll
        for (int nt = 0; nt < 8; nt++) {
            tm0 = fmaxf(tm0, fmaxf(sacc[nt][0], sacc[nt][1]));
            tm1 = fmaxf(tm1, fmaxf(sacc[nt][2], sacc[nt][3]));
        }
        tm0 = fmaxf(tm0, __shfl_xor_sync(0xffffffffu, tm0, 1));
        tm0 = fmaxf(tm0, __shfl_xor_sync(0xffffffffu, tm0, 2));
        tm1 = fmaxf(tm1, __shfl_xor_sync(0xffffffffu, tm1, 1));
        tm1 = fmaxf(tm1, __shfl_xor_sync(0xffffffffu, tm1, 2));
        float mn0 = fmaxf(mrow0, tm0), mn1 = fmaxf(mrow1, tm1);
        float cr0 = __expf(mrow0 - mn0), cr1 = __expf(mrow1 - mn1);
        float sum0 = 0.f, sum1 = 0.f;
        #pragma unroll
        for (int nt = 0; nt < 8; nt++) {
            sacc[nt][0] = __expf(sacc[nt][0] - mn0);
            sacc[nt][1] = __expf(sacc[nt][1] - mn0);
            sacc[nt][2] = __expf(sacc[nt][2] - mn1);
            sacc[nt][3] = __expf(sacc[nt][3] - mn1);
            sum0 += sacc[nt][0] + sacc[nt][1];
            sum1 += sacc[nt][2] + sacc[nt][3];
        }
        sum0 += __shfl_xor_sync(0xffffffffu, sum0, 1);
        sum0 += __shfl_xor_sync(0xffffffffu, sum0, 2);
        sum1 += __shfl_xor_sync(0xffffffffu, sum1, 1);
        sum1 += __shfl_xor_sync(0xffffffffu, sum1, 2);
        lrow0 = lrow0 * cr0 + sum0; mrow0 = mn0;
        lrow1 = lrow1 * cr1 + sum1; mrow1 = mn1;
        #pragma unroll
        for (int nt = 0; nt < 8; nt++) {
            oacc[nt][0] *= cr0; oacc[nt][1] *= cr0;
            oacc[nt][2] *= cr1; oacc[nt][3] *= cr1;
        }
        /* ---- P (bf16) -> per-warp smem ---- */
        {
            const uint32_t pr0 = qp + (w * 16 + g) * 128;
            const uint32_t pr1 = qp + (w * 16 + g + 8) * 128;
            #pragma unroll
            for (int nt = 0; nt < 8; nt++) {
                uint32_t off = ((nt ^ g) << 4) + t * 4;
                *(uint32_t*)(fsm + (pr0 + off - sb)) = pack_bf16(sacc[nt][0], sacc[nt][1]);
                *(uint32_t*)(fsm + (pr1 + off - sb)) = pack_bf16(sacc[nt][2], sacc[nt][3]);
            }
        }
        __syncwarp();
        /* ---- O += P V ---- */
        #pragma unroll
        for (int ks = 0; ks < 4; ks++) {
            uint32_t pf[4];
            {
                int R = w * 16 + paR;
                ldsm4(pf, qp + R * 128 + (((ks * 2 + paH) ^ (R & 7)) << 4));
            }
            #pragma unroll
            for (int np = 0; np < 4; np++) {
                uint32_t bv[4];
                int R = ks * 16 + vbR;
                ldsm4t(bv, vbuf + R * 128 + (((np * 2 + vbH) ^ (R & 7)) << 4));
                mma_bf16(oacc[np * 2 + 0], pf, &bv[0]);
                mma_bf16(oacc[np * 2 + 1], pf, &bv[2]);
            }
        }
        __syncthreads();
    }
    #undef KVSTAGE

    /* epilogue */
    float inv0 = 1.f / lrow0, inv1 = 1.f / lrow1;
    float* ob = O + (size_t)(b * SS + qt * FBM) * DD + h * DKK;
    int r0 = w * 16 + g;
    #pragma unroll
    for (int nt = 0; nt < 8; nt++) {
        int col = nt * 8 + 2 * t;
        *(float2*)(ob + (size_t)r0 * DD + col) =
            make_float2(tf32r(oacc[nt][0] * inv0), tf32r(oacc[nt][1] * inv0));
        *(float2*)(ob + (size_t)(r0 + 8) * DD + col) =
            make_float2(tf32r(oacc[nt][2] * inv1), tf32r(oacc[nt][3] * inv1));
    }
}

/* ---------------- host orchestration (graph-capturable) ------------------- */
extern "C" void kernel_launch(void* const* d_in, const int* in_sizes, int n_in,
                              void* d_out, int out_size) {
    (void)in_sizes; (void)n_in; (void)out_size;
    const float* x    = (const float*)d_in[0];
    const int*   mask = (const int*)  d_in[1];
    const float* wq   = (const float*)d_in[2];
    const float* bq   = (const float*)d_in[3];
    const float* wk   = (const float*)d_in[4];
    const float* bk   = (const float*)d_in[5];
    const float* wv   = (const float*)d_in[6];
    const float* bv   = (const float*)d_in[7];
    const float* wo   = (const float*)d_in[8];
    const float* bo   = (const float*)d_in[9];
    const float* w1   = (const float*)d_in[10];
    const float* b1   = (const float*)d_in[11];
    const float* w2   = (const float*)d_in[12];
    const float* b2   = (const float*)d_in[13];
    const float* a1   = (const float*)d_in[14];
    const float* c1   = (const float*)d_in[15];
    const float* a2   = (const float*)d_in[16];
    const float* c2   = (const float*)d_in[17];
    float* out = (float*)d_out;

    float *ln1, *attn, *h, *ln2, *ffn;
    __nv_bfloat16 *q, *k, *v;
    float *wqc, *wkc, *wvc, *woc, *w1c, *w2c;
    cudaGetSymbolAddress((void**)&ln1,  g_ln1);
    cudaGetSymbolAddress((void**)&q,    g_qb);
    cudaGetSymbolAddress((void**)&k,    g_kb);
    cudaGetSymbolAddress((void**)&v,    g_vb);
    cudaGetSymbolAddress((void**)&attn, g_attn);
    cudaGetSymbolAddress((void**)&h,    g_h);
    cudaGetSymbolAddress((void**)&ln2,  g_ln2);
    cudaGetSymbolAddress((void**)&ffn,  g_ffn);
    cudaGetSymbolAddress((void**)&wqc,  g_wqc);
    cudaGetSymbolAddress((void**)&wkc,  g_wkc);
    cudaGetSymbolAddress((void**)&wvc,  g_wvc);
    cudaGetSymbolAddress((void**)&woc,  g_woc);
    cudaGetSymbolAddress((void**)&w1c,  g_w1c);
    cudaGetSymbolAddress((void**)&w2c,  g_w2c);

    cudaFuncSetAttribute(flash_bf16,
                         cudaFuncAttributeMaxDynamicSharedMemorySize, FSMEM);
    cudaFuncSetAttribute(gemm_tc<false,false,false,true>,
                         cudaFuncAttributeMaxDynamicSharedMemorySize, GSMEM);
    cudaFuncSetAttribute(gemm_tc<false,true,false,false>,
                         cudaFuncAttributeMaxDynamicSharedMemorySize, GSMEM);
    cudaFuncSetAttribute(gemm_tc<true,false,true,false>,
                         cudaFuncAttributeMaxDynamicSharedMemorySize, GSMEM);

    /* weight tf32 pre-rounding */
    cvt_tf32_kernel<<<(DD*DD/4)/256,   256>>>(wq, wqc, DD*DD/4);
    cvt_tf32_kernel<<<(DD*DD/4)/256,   256>>>(wk, wkc, DD*DD/4);
    cvt_tf32_kernel<<<(DD*DD/4)/256,   256>>>(wv, wvc, DD*DD/4);
    cvt_tf32_kernel<<<(DD*DD/4)/256,   256>>>(wo, woc, DD*DD/4);
    cvt_tf32_kernel<<<(DFFN*DD/4)/256, 256>>>(w1, w1c, DFFN*DD/4);
    cvt_tf32_kernel<<<(DFFN*DD/4)/256, 256>>>(w2, w2c, DFFN*DD/4);

    /* LN1 */
    ln_kernel<<<NTOK, 256>>>(x, a1, c1, ln1);
    /* Q,K,V projections -> bf16 */
    dim3 gq(DD / TBN, NTOK / TBM);
    gemm_tc<false,false,false,true><<<gq, 256, GSMEM>>>(ln1, wqc, bq, nullptr, q, NTOK, DD, DD);
    gemm_tc<false,false,false,true><<<gq, 256, GSMEM>>>(ln1, wkc, bk, nullptr, k, NTOK, DD, DD);
    gemm_tc<false,false,false,true><<<gq, 256, GSMEM>>>(ln1, wvc, bv, nullptr, v, NTOK, DD, DD);
    /* attention (bf16 in, tf32-rounded fp32 out) */
    flash_bf16<<<dim3(SS / FBM, HH, BB), 256, FSMEM>>>(q, k, v, mask, attn);
    /* h = x + attn @ wo^T + bo */
    gemm_tc<false,true,false,false><<<gq, 256, GSMEM>>>(attn, woc, bo, x, h, NTOK, DD, DD);
    /* LN2 */
    ln_kernel<<<NTOK, 256>>>(h, a2, c2, ln2);
    /* ffn = relu(ln2 @ w1^T + b1) */
    gemm_tc<true,false,true,false><<<dim3(DFFN / TBN, NTOK / TBM), 256, GSMEM>>>(
        ln2, w1c, b1, nullptr, ffn, NTOK, DFFN, DD);
    /* out = h + ffn @ w2^T + b2 */
    gemm_tc<false,true,false,false><<<gq, 256, GSMEM>>>(ffn, w2c, b2, h, out, NTOK, DD, DFFN);
}

// round 12
// speedup vs baseline: 4.9287x; 1.1087x over previous
#include <cuda_runtime.h>
#include <cuda_bf16.h>
#include <math.h>
#include <stdint.h>

#define BB   4
#define SS   2048
#define DD   1024
#define HH   16
#define DKK  64
#define DFFN 4096
#define NTOK (BB*SS)
#define LNEPS 1e-6f

/* ---------------- scratch (alloc-free: __device__ globals) ---------------- */
__device__ __nv_bfloat16 g_ln1b[NTOK*DD];
__device__ __nv_bfloat16 g_qb[NTOK*DD];
__device__ __nv_bfloat16 g_kb[NTOK*DD];
__device__ __nv_bfloat16 g_vb[NTOK*DD];
__device__ float g_attn[NTOK*DD];
__device__ float g_h   [NTOK*DD];
__device__ float g_ln2 [NTOK*DD];
__device__ float g_ffn [(size_t)NTOK*DFFN];
__device__ __nv_bfloat16 g_wqb[DD*DD];
__device__ __nv_bfloat16 g_wkb[DD*DD];
__device__ __nv_bfloat16 g_wvb[DD*DD];
__device__ float g_woc[DD*DD];
__device__ float g_w1c[DFFN*DD];
__device__ float g_w2c[DD*DFFN];

/* ---------------- helpers ------------------------------------------------- */
__device__ __forceinline__ uint32_t f2tf32(float f) {
    uint32_t u;
    asm("cvt.rna.tf32.f32 %0, %1;" : "=r"(u) : "f"(f));
    return u;
}
__device__ __forceinline__ float tf32r(float f) {
    return __uint_as_float(f2tf32(f));
}
__device__ __forceinline__ uint32_t pack_bf16(float lo, float hi) {
    uint32_t r;
    asm("cvt.rn.bf16x2.f32 %0, %1, %2;" : "=r"(r) : "f"(hi), "f"(lo));
    return r;
}
__device__ __forceinline__ void mma_tf32(float* c, const uint32_t* a, const uint32_t* b) {
    asm volatile(
        "mma.sync.aligned.m16n8k8.row.col.f32.tf32.tf32.f32 "
        "{%0,%1,%2,%3}, {%4,%5,%6,%7}, {%8,%9}, {%0,%1,%2,%3};"
        : "+f"(c[0]), "+f"(c[1]), "+f"(c[2]), "+f"(c[3])
        : "r"(a[0]), "r"(a[1]), "r"(a[2]), "r"(a[3]), "r"(b[0]), "r"(b[1]));
}
__device__ __forceinline__ void mma_bf16(float* c, const uint32_t* a, const uint32_t* b) {
    asm volatile(
        "mma.sync.aligned.m16n8k16.row.col.f32.bf16.bf16.f32 "
        "{%0,%1,%2,%3}, {%4,%5,%6,%7}, {%8,%9}, {%0,%1,%2,%3};"
        : "+f"(c[0]), "+f"(c[1]), "+f"(c[2]), "+f"(c[3])
        : "r"(a[0]), "r"(a[1]), "r"(a[2]), "r"(a[3]), "r"(b[0]), "r"(b[1]));
}
__device__ __forceinline__ void cp16s(uint32_t saddr, const void* g) {
    asm volatile("cp.async.cg.shared.global [%0], [%1], 16;" :: "r"(saddr), "l"(g));
}
__device__ __forceinline__ uint32_t smem_u32(const void* p) {
    return (uint32_t)__cvta_generic_to_shared(p);
}
__device__ __forceinline__ void ldsm4(uint32_t* r, uint32_t addr) {
    asm volatile("ldmatrix.sync.aligned.m8n8.x4.shared.b16 {%0,%1,%2,%3}, [%4];"
        : "=r"(r[0]), "=r"(r[1]), "=r"(r[2]), "=r"(r[3]) : "r"(addr));
}
__device__ __forceinline__ void ldsm4t(uint32_t* r, uint32_t addr) {
    asm volatile("ldmatrix.sync.aligned.m8n8.x4.trans.shared.b16 {%0,%1,%2,%3}, [%4];"
        : "=r"(r[0]), "=r"(r[1]), "=r"(r[2]), "=r"(r[3]) : "r"(addr));
}

/* ---------------- weight pre-rounding ------------------------------------- */
__global__ void cvt_tf32_kernel(const float* __restrict__ src,
                                float* __restrict__ dst, int n4) {
    int i = blockIdx.x * 256 + threadIdx.x;
    if (i < n4) {
        float4 v = ((const float4*)src)[i];
        float4 o;
        o.x = tf32r(v.x); o.y = tf32r(v.y); o.z = tf32r(v.z); o.w = tf32r(v.w);
        ((float4*)dst)[i] = o;
    }
}
__global__ void cvt_bf16_kernel(const float* __restrict__ src,
                                __nv_bfloat16* __restrict__ dst, int n4) {
    int i = blockIdx.x * 256 + threadIdx.x;
    if (i < n4) {
        float4 v = ((const float4*)src)[i];
        uint2 o;
        o.x = pack_bf16(v.x, v.y);
        o.y = pack_bf16(v.z, v.w);
        ((uint2*)dst)[i] = o;
    }
}

/* ---------------- LayerNorm ------------------------------------------------ */
template<bool BF16OUT>
__global__ void ln_kernel(const float* __restrict__ x,
                          const float* __restrict__ ap,
                          const float* __restrict__ cp,
                          void* __restrict__ y) {
    __shared__ float sred[16];
    int row = blockIdx.x;
    int tid = threadIdx.x;
    const float4 v = ((const float4*)(x + (size_t)row*DD))[tid];
    float s  = v.x + v.y + v.z + v.w;
    float sq = v.x*v.x + v.y*v.y + v.z*v.z + v.w*v.w;
    #pragma unroll
    for (int off = 16; off > 0; off >>= 1) {
        s  += __shfl_xor_sync(0xffffffffu, s,  off);
        sq += __shfl_xor_sync(0xffffffffu, sq, off);
    }
    int warp = tid >> 5, lane = tid & 31;
    if (lane == 0) { sred[warp] = s; sred[warp + 8] = sq; }
    __syncthreads();
    float st = 0.f, sqt = 0.f;
    #pragma unroll
    for (int i = 0; i < 8; i++) { st += sred[i]; sqt += sred[i + 8]; }
    float mean = st * (1.0f / DD);
    float var  = (sqt - (float)DD * mean * mean) * (1.0f / (DD - 1));
    float stdv = sqrtf(fmaxf(var, 0.f));
    float inv  = ap[0] / (stdv + LNEPS);
    float beta = cp[0];
    float o0 = (v.x - mean) * inv + beta;
    float o1 = (v.y - mean) * inv + beta;
    float o2 = (v.z - mean) * inv + beta;
    float o3 = (v.w - mean) * inv + beta;
    if (BF16OUT) {
        uint2 o;
        o.x = pack_bf16(o0, o1);
        o.y = pack_bf16(o2, o3);
        ((uint2*)((__nv_bfloat16*)y + (size_t)row*DD))[tid] = o;
    } else {
        float4 o = make_float4(tf32r(o0), tf32r(o1), tf32r(o2), tf32r(o3));
        ((float4*)((float*)y + (size_t)row*DD))[tid] = o;
    }
}

/* ========== TF32 TC NT GEMM: 128x256 CTA, ldmatrix, SW128, cp.async ======== */
#define TBM 128
#define TBN 256
#define A_STG 16384
#define B_STG 32768
#define GSMEM (2 * (A_STG + B_STG))   /* 96 KB */

template<bool RELU, bool RES, bool TFOUT, bool BF16OUT>
__global__ void __launch_bounds__(256)
gemm_tc(const float* __restrict__ A, const float* __restrict__ Bw,
        const float* __restrict__ bias, const float* __restrict__ res,
        void* __restrict__ Cv, int M, int N, int K) {
    extern __shared__ __align__(1024) float sm[];
    const int tid = threadIdx.x;
    const int warp = tid >> 5, lane = tid & 31;
    const int g = lane >> 2, t = lane & 3;
    const int wm = warp & 1, wn = warp >> 1;
    const int bm = blockIdx.y, bn = blockIdx.x;

    const uint32_t smbase = smem_u32(sm);
    const uint32_t aoff[2] = { smbase,               smbase + A_STG };
    const uint32_t boff[2] = { smbase + 2 * A_STG,   smbase + 2 * A_STG + B_STG };

    const float* Ab = A  + (size_t)(bm * TBM) * K;
    const float* Bb = Bw + (size_t)(bn * TBN) * K;
    const int ntiles = K / 32;

    float acc[4][8][4] = {};

    const int aR = lane & 15;
    const int aH = lane >> 4;
    const int bR = ((lane >> 4) << 3) + (lane & 7);
    const int bH = (lane >> 3) & 1;
    const int lx = lane & 7;

    #define STAGE(buf, k0)                                                     \
    {                                                                          \
        _Pragma("unroll")                                                      \
        for (int i = 0; i < 4; i++) {                                          \
            int s = tid + i * 256;                                             \
            int r = s >> 3, c = s & 7;                                         \
            cp16s(aoff[buf] + r * 128 + (((c ^ (r & 7)) << 4)),                \
                  Ab + (size_t)r * K + (k0) + c * 4);                          \
        }                                                                      \
        _Pragma("unroll")                                                      \
        for (int i = 0; i < 8; i++) {                                          \
            int s = tid + i * 256;                                             \
            int r = s >> 3, c = s & 7;                                         \
            cp16s(boff[buf] + r * 128 + (((c ^ (r & 7)) << 4)),                \
                  Bb + (size_t)r * K + (k0) + c * 4);                          \
        }                                                                      \
    }

    STAGE(0, 0);
    asm volatile("cp.async.commit_group;");

    for (int kt = 0; kt < ntiles; kt++) {
        if (kt + 1 < ntiles) {
            STAGE((kt + 1) & 1, (kt + 1) * 32);
            asm volatile("cp.async.commit_group;");
            asm volatile("cp.async.wait_group 1;");
        } else {
            asm volatile("cp.async.commit_group;");
            asm volatile("cp.async.wait_group 0;");
        }
        __syncthreads();
        const uint32_t ab = aoff[kt & 1], bb = boff[kt & 1];
        #pragma unroll
        for (int ks4 = 0; ks4 < 8; ks4 += 2) {
            uint32_t af[4][4], bf[4][4];
            #pragma unroll
            for (int mt = 0; mt < 4; mt++) {
                int R = wm * 64 + mt * 16 + aR;
                ldsm4(af[mt], ab + R * 128 + ((((ks4 + aH) ^ lx)) << 4));
            }
            #pragma unroll
            for (int jp = 0; jp < 4; jp++) {
                int R = wn * 64 + jp * 16 + bR;
                ldsm4(bf[jp], bb + R * 128 + ((((ks4 + bH) ^ lx)) << 4));
            }
            #pragma unroll
            for (int mt = 0; mt < 4; mt++)
                #pragma unroll
                for (int nt = 0; nt < 8; nt++)
                    mma_tf32(acc[mt][nt], af[mt], &bf[nt >> 1][(nt & 1) * 2]);
        }
        __syncthreads();
    }
    #undef STAGE

    /* epilogue */
    #pragma unroll
    for (int mt = 0; mt < 4; mt++) {
        #pragma unroll
        for (int nt = 0; nt < 8; nt++) {
            int col = bn * TBN + wn * 64 + nt * 8 + t * 2;
            float bx = bias[col], by = bias[col + 1];
            #pragma unroll
            for (int half = 0; half < 2; half++) {
                size_t row = (size_t)(bm * TBM + wm * 64 + mt * 16 + g + half * 8);
                float ox = acc[mt][nt][half * 2 + 0] + bx;
                float oy = acc[mt][nt][half * 2 + 1] + by;
                if (RELU) { ox = fmaxf(ox, 0.f); oy = fmaxf(oy, 0.f); }
                if (TFOUT) { ox = tf32r(ox); oy = tf32r(oy); }
                if (RES) {
                    float2 r2 = *(const float2*)(res + row * N + col);
                    ox += r2.x; oy += r2.y;
                }
                if (BF16OUT) {
                    *(uint32_t*)((__nv_bfloat16*)Cv + row * N + col) = pack_bf16(ox, oy);
                } else {
                    *(float2*)((float*)Cv + row * N + col) = make_float2(ox, oy);
                }
            }
        }
    }
}

/* ========== BF16 TC NT GEMM: 128x256 CTA, TBK=64 (128B rows) =============== */
template<bool RELU, bool RES, bool BF16OUT>
__global__ void __launch_bounds__(256)
gemm_bf(const __nv_bfloat16* __restrict__ A, const __nv_bfloat16* __restrict__ Bw,
        const float* __restrict__ bias, const float* __restrict__ res,
        void* __restrict__ Cv, int M, int N, int K) {
    extern __shared__ __align__(1024) float sm[];
    const int tid = threadIdx.x;
    const int warp = tid >> 5, lane = tid & 31;
    const int g = lane >> 2, t = lane & 3;
    const int wm = warp & 1, wn = warp >> 1;
    const int bm = blockIdx.y, bn = blockIdx.x;

    const uint32_t smbase = smem_u32(sm);
    const uint32_t aoff[2] = { smbase,               smbase + A_STG };
    const uint32_t boff[2] = { smbase + 2 * A_STG,   smbase + 2 * A_STG + B_STG };

    const __nv_bfloat16* Ab = A  + (size_t)(bm * TBM) * K;
    const __nv_bfloat16* Bb = Bw + (size_t)(bn * TBN) * K;
    const int ntiles = K / 64;

    float acc[4][8][4] = {};

    const int aR = lane & 15;
    const int aH = lane >> 4;
    const int bR = ((lane >> 4) << 3) + (lane & 7);
    const int bH = (lane >> 3) & 1;

    #define BSTAGE(buf, k0)                                                    \
    {                                                                          \
        _Pragma("unroll")                                                      \
        for (int i = 0; i < 4; i++) {                                          \
            int s = tid + i * 256;                                             \
            int r = s >> 3, c = s & 7;                                         \
            cp16s(aoff[buf] + r * 128 + (((c ^ (r & 7)) << 4)),                \
                  Ab + (size_t)r * K + (k0) + c * 8);                          \
        }                                                                      \
        _Pragma("unroll")                                                      \
        for (int i = 0; i < 8; i++) {                                          \
            int s = tid + i * 256;                                             \
            int r = s >> 3, c = s & 7;                                         \
            cp16s(boff[buf] + r * 128 + (((c ^ (r & 7)) << 4)),                \
                  Bb + (size_t)r * K + (k0) + c * 8);                          \
        }                                                                      \
    }

    BSTAGE(0, 0);
    asm volatile("cp.async.commit_group;");

    for (int kt = 0; kt < ntiles; kt++) {
        if (kt + 1 < ntiles) {
            BSTAGE((kt + 1) & 1, (kt + 1) * 64);
            asm volatile("cp.async.commit_group;");
            asm volatile("cp.async.wait_group 1;");
        } else {
            asm volatile("cp.async.commit_group;");
            asm volatile("cp.async.wait_group 0;");
        }
        __syncthreads();
        const uint32_t ab = aoff[kt & 1], bb = boff[kt & 1];
        #pragma unroll
        for (int ks = 0; ks < 4; ks++) {
            uint32_t af[4][4], bf[4][4];
            #pragma unroll
            for (int mt = 0; mt < 4; mt++) {
                int R = wm * 64 + mt * 16 + aR;
                ldsm4(af[mt], ab + R * 128 + (((ks * 2 + aH) ^ (R & 7)) << 4));
            }
            #pragma unroll
            for (int jp = 0; jp < 4; jp++) {
                int R = wn * 64 + jp * 16 + bR;
                ldsm4(bf[jp], bb + R * 128 + (((ks * 2 + bH) ^ (R & 7)) << 4));
            }
            #pragma unroll
            for (int mt = 0; mt < 4; mt++)
                #pragma unroll
                for (int nt = 0; nt < 8; nt++)
                    mma_bf16(acc[mt][nt], af[mt], &bf[nt >> 1][(nt & 1) * 2]);
        }
        __syncthreads();
    }
    #undef BSTAGE

    /* epilogue */
    #pragma unroll
    for (int mt = 0; mt < 4; mt++) {
        #pragma unroll
        for (int nt = 0; nt < 8; nt++) {
            int col = bn * TBN + wn * 64 + nt * 8 + t * 2;
            float bx = bias[col], by = bias[col + 1];
            #pragma unroll
            for (int half = 0; half < 2; half++) {
                size_t row = (size_t)(bm * TBM + wm * 64 + mt * 16 + g + half * 8);
                float ox = acc[mt][nt][half * 2 + 0] + bx;
                float oy = acc[mt][nt][half * 2 + 1] + by;
                if (RELU) { ox = fmaxf(ox, 0.f); oy = fmaxf(oy, 0.f); }
                if (RES) {
                    float2 r2 = *(const float2*)(res + row * N + col);
                    ox += r2.x; oy += r2.y;
                }
                if (BF16OUT) {
                    *(uint32_t*)((__nv_bfloat16*)Cv + row * N + col) = pack_bf16(ox, oy);
                } else {
                    *(float2*)((float*)Cv + row * N + col) = make_float2(ox, oy);
                }
            }
        }
    }
}

/* ================= bf16 flash attention (unchanged from R9) =============== */
#define FBM 128
#define FBN 64
#define FNT (SS / FBN)
#define FQP   0
#define FK    16384
#define FV    (16384 + 2 * 8192)
#define FSMEM (16384 + 4 * 8192)

__global__ void __launch_bounds__(256, 1)
flash_bf16(const __nv_bfloat16* __restrict__ Q,
           const __nv_bfloat16* __restrict__ Kg,
           const __nv_bfloat16* __restrict__ Vg,
           const int* __restrict__ mask, float* __restrict__ O) {
    extern __shared__ __align__(1024) char fsm[];
    const uint32_t sb = smem_u32(fsm);
    const uint32_t qp = sb + FQP;
    const uint32_t koff[2] = { sb + FK, sb + FK + 8192 };
    const uint32_t voff[2] = { sb + FV, sb + FV + 8192 };

    const int qt = blockIdx.x, h = blockIdx.y, b = blockIdx.z;
    const int tid = threadIdx.x;
    const int w = tid >> 5, lane = tid & 31, g = lane >> 2, t = lane & 3;

    const __nv_bfloat16* qb = Q + (size_t)(b * SS + qt * FBM) * DD + h * DKK;
    #pragma unroll
    for (int i = 0; i < 4; i++) {
        int s = tid + i * 256;
        int r = s >> 3, c = s & 7;
        *(uint4*)(fsm + FQP + r * 128 + ((c ^ (r & 7)) << 4)) =
            *(const uint4*)(qb + (size_t)r * DD + c * 8);
    }
    __syncthreads();
    uint32_t qf[4][4];
    {
        const int R = w * 16 + (lane & 15);
        const int hh = lane >> 4;
        #pragma unroll
        for (int ks = 0; ks < 4; ks++)
            ldsm4(qf[ks], qp + R * 128 + (((ks * 2 + hh) ^ (R & 7)) << 4));
    }
    __syncthreads();

    const __nv_bfloat16* kb = Kg + (size_t)(b * SS) * DD + h * DKK;
    const __nv_bfloat16* vb = Vg + (size_t)(b * SS) * DD + h * DKK;
    #define KVSTAGE(buf, kt)                                                   \
    {                                                                          \
        const __nv_bfloat16* kg = kb + (size_t)((kt) * FBN) * DD;              \
        const __nv_bfloat16* vg = vb + (size_t)((kt) * FBN) * DD;              \
        _Pragma("unroll")                                                      \
        for (int i = 0; i < 2; i++) {                                          \
            int s = tid + i * 256;                                             \
            int r = s >> 3, c = s & 7;                                         \
            cp16s(koff[buf] + r * 128 + ((c ^ (r & 7)) << 4),                  \
                  kg + (size_t)r * DD + c * 8);                                \
            cp16s(voff[buf] + r * 128 + ((c ^ (r & 7)) << 4),                  \
                  vg + (size_t)r * DD + c * 8);                                \
        }                                                                      \
    }
    KVSTAGE(0, 0);
    asm volatile("cp.async.commit_group;");

    float oacc[8][4] = {};
    float mrow0 = -1e30f, mrow1 = -1e30f, lrow0 = 0.f, lrow1 = 0.f;
    const int* mp = mask + b * SS;

    const int kbR = (lane & 7) + ((lane >> 4) << 3);
    const int kbH = (lane >> 3) & 1;
    const int vbR = (lane & 7) + (((lane >> 3) & 1) << 3);
    const int vbH = lane >> 4;
    const int paR = lane & 15, paH = lane >> 4;

    for (int kt = 0; kt < FNT; kt++) {
        if (kt + 1 < FNT) {
            KVSTAGE((kt + 1) & 1, kt + 1);
            asm volatile("cp.async.commit_group;");
            asm volatile("cp.async.wait_group 1;");
        } else {
            asm volatile("cp.async.commit_group;");
            asm volatile("cp.async.wait_group 0;");
        }
        __syncthreads();
        const uint32_t kbuf = koff[kt & 1], vbuf = voff[kt & 1];

        float sacc[8][4] = {};
        #pragma unroll
        for (int ks = 0; ks < 4; ks++) {
            #pragma unroll
            for (int np = 0; np < 4; np++) {
                uint32_t bf[4];
                int R = np * 16 + kbR;
                ldsm4(bf, kbuf + R * 128 + (((ks * 2 + kbH) ^ (R & 7)) << 4));
                mma_bf16(sacc[np * 2 + 0], qf[ks], &bf[0]);
                mma_bf16(sacc[np * 2 + 1], qf[ks], &bf[2]);
            }
        }
        #pragma unroll
        for (int nt = 0; nt < 8; nt++) {
            int mj0 = __ldg(mp + kt * FBN + nt * 8 + 2 * t);
            int mj1 = __ldg(mp + kt * FBN + nt * 8 + 2 * t + 1);
            sacc[nt][0] = mj0 ? sacc[nt][0] * 0.125f : -1e9f;
            sacc[nt][1] = mj1 ? sacc[nt][1] * 0.125f : -1e9f;
            sacc[nt][2] = mj0 ? sacc[nt][2] * 0.125f : -1e9f;
            sacc[nt][3] = mj1 ? sacc[nt][3] * 0.125f : -1e9f;
        }
        float tm0 = -1e30f, tm1 = -1e30f;
        #pragma unroll
        for (int nt = 0; nt < 8; nt++) {
            tm0 = fmaxf(tm0, fmaxf(sacc[nt][0], sacc[nt][1]));
            tm1 = fmaxf(tm1, fmaxf(sacc[nt][2], sacc[nt][3]));
        }
        tm0 = fmaxf(tm0, __shfl_xor_sync(0xffffffffu, tm0, 1));
        tm0 = fmaxf(tm0, __shfl_xor_sync(0xffffffffu, tm0, 2));
        tm1 = fmaxf(tm1, __shfl_xor_sync(0xffffffffu, tm1, 1));
        tm1 = fmaxf(tm1, __shfl_xor_sync(0xffffffffu, tm1, 2));
        float mn0 = fmaxf(mrow0, tm0), mn1 = fmaxf(mrow1, tm1);
        float cr0 = __expf(mrow0 - mn0), cr1 = __expf(mrow1 - mn1);
        float sum0 = 0.f, sum1 = 0.f;
        #pragma unroll
        for (int nt = 0; nt < 8; nt++) {
            sacc[nt][0] = __expf(sacc[nt][0] - mn0);
            sacc[nt][1] = __expf(sacc[nt][1] - mn0);
            sacc[nt][2] = __expf(sacc[nt][2] - mn1);
            sacc[nt][3] = __expf(sacc[nt][3] - mn1);
            sum0 += sacc[nt][0] + sacc[nt][1];
            sum1 += sacc[nt][2] + sacc[nt][3];
        }
        sum0 += __shfl_xor_sync(0xffffffffu, sum0, 1);
        sum0 += __shfl_xor_sync(0xffffffffu, sum0, 2);
        sum1 += __shfl_xor_sync(0xffffffffu, sum1, 1);
        sum1 += __shfl_xor_sync(0xffffffffu, sum1, 2);
        lrow0 = lrow0 * cr0 + sum0; mrow0 = mn0;
        lrow1 = lrow1 * cr1 + sum1; mrow1 = mn1;
        #pragma unroll
        for (int nt = 0; nt < 8; nt++) {
            oacc[nt][0] *= cr0; oacc[nt][1] *= cr0;
            oacc[nt][2] *= cr1; oacc[nt][3] *= cr1;
        }
        {
            const uint32_t pr0 = qp + (w * 16 + g) * 128;
            const uint32_t pr1 = qp + (w * 16 + g + 8) * 128;
            #pragma unroll
            for (int nt = 0; nt < 8; nt++) {
                uint32_t off = ((nt ^ g) << 4) + t * 4;
                *(uint32_t*)(fsm + (pr0 + off - sb)) = pack_bf16(sacc[nt][0], sacc[nt][1]);
                *(uint32_t*)(fsm + (pr1 + off - sb)) = pack_bf16(sacc[nt][2], sacc[nt][3]);
            }
        }
        __syncwarp();
        #pragma unroll
        for (int ks = 0; ks < 4; ks++) {
            uint32_t pf[4];
            {
                int R = w * 16 + paR;
                ldsm4(pf, qp + R * 128 + (((ks * 2 + paH) ^ (R & 7)) << 4));
            }
            #pragma unroll
            for (int np = 0; np < 4; np++) {
                uint32_t bv[4];
                int R = ks * 16 + vbR;
                ldsm4t(bv, vbuf + R * 128 + (((np * 2 + vbH) ^ (R & 7)) << 4));
                mma_bf16(oacc[np * 2 + 0], pf, &bv[0]);
                mma_bf16(oacc[np * 2 + 1], pf, &bv[2]);
            }
        }
        __syncthreads();
    }
    #undef KVSTAGE

    float inv0 = 1.f / lrow0, inv1 = 1.f / lrow1;
    float* ob = O + (size_t)(b * SS + qt * FBM) * DD + h * DKK;
    int r0 = w * 16 + g;
    #pragma unroll
    for (int nt = 0; nt < 8; nt++) {
        int col = nt * 8 + 2 * t;
        *(float2*)(ob + (size_t)r0 * DD + col) =
            make_float2(tf32r(oacc[nt][0] * inv0), tf32r(oacc[nt][1] * inv0));
        *(float2*)(ob + (size_t)(r0 + 8) * DD + col) =
            make_float2(tf32r(oacc[nt][2] * inv1), tf32r(oacc[nt][3] * inv1));
    }
}

/* ---------------- host orchestration (graph-capturable) ------------------- */
extern "C" void kernel_launch(void* const* d_in, const int* in_sizes, int n_in,
                              void* d_out, int out_size) {
    (void)in_sizes; (void)n_in; (void)out_size;
    const float* x    = (const float*)d_in[0];
    const int*   mask = (const int*)  d_in[1];
    const float* wq   = (const float*)d_in[2];
    const float* bq   = (const float*)d_in[3];
    const float* wk   = (const float*)d_in[4];
    const float* bk   = (const float*)d_in[5];
    const float* wv   = (const float*)d_in[6];
    const float* bv   = (const float*)d_in[7];
    const float* wo   = (const float*)d_in[8];
    const float* bo   = (const float*)d_in[9];
    const float* w1   = (const float*)d_in[10];
    const float* b1   = (const float*)d_in[11];
    const float* w2   = (const float*)d_in[12];
    const float* b2   = (const float*)d_in[13];
    const float* a1   = (const float*)d_in[14];
    const float* c1   = (const float*)d_in[15];
    const float* a2   = (const float*)d_in[16];
    const float* c2   = (const float*)d_in[17];
    float* out = (float*)d_out;

    float *attn, *h, *ln2, *ffn, *woc, *w1c, *w2c;
    __nv_bfloat16 *ln1b, *q, *k, *v, *wqb, *wkb, *wvb;
    cudaGetSymbolAddress((void**)&ln1b, g_ln1b);
    cudaGetSymbolAddress((void**)&q,    g_qb);
    cudaGetSymbolAddress((void**)&k,    g_kb);
    cudaGetSymbolAddress((void**)&v,    g_vb);
    cudaGetSymbolAddress((void**)&attn, g_attn);
    cudaGetSymbolAddress((void**)&h,    g_h);
    cudaGetSymbolAddress((void**)&ln2,  g_ln2);
    cudaGetSymbolAddress((void**)&ffn,  g_ffn);
    cudaGetSymbolAddress((void**)&wqb,  g_wqb);
    cudaGetSymbolAddress((void**)&wkb,  g_wkb);
    cudaGetSymbolAddress((void**)&wvb,  g_wvb);
    cudaGetSymbolAddress((void**)&woc,  g_woc);
    cudaGetSymbolAddress((void**)&w1c,  g_w1c);
    cudaGetSymbolAddress((void**)&w2c,  g_w2c);

    cudaFuncSetAttribute(flash_bf16,
                         cudaFuncAttributeMaxDynamicSharedMemorySize, FSMEM);
    cudaFuncSetAttribute(gemm_bf<false,false,true>,
                         cudaFuncAttributeMaxDynamicSharedMemorySize, GSMEM);
    cudaFuncSetAttribute(gemm_tc<false,true,false,false>,
                         cudaFuncAttributeMaxDynamicSharedMemorySize, GSMEM);
    cudaFuncSetAttribute(gemm_tc<true,false,true,false>,
                         cudaFuncAttributeMaxDynamicSharedMemorySize, GSMEM);

    /* weight pre-rounding: QKV -> bf16; wo/w1/w2 -> tf32 */
    cvt_bf16_kernel<<<(DD*DD/4)/256,   256>>>(wq, wqb, DD*DD/4);
    cvt_bf16_kernel<<<(DD*DD/4)/256,   256>>>(wk, wkb, DD*DD/4);
    cvt_bf16_kernel<<<(DD*DD/4)/256,   256>>>(wv, wvb, DD*DD/4);
    cvt_tf32_kernel<<<(DD*DD/4)/256,   256>>>(wo, woc, DD*DD/4);
    cvt_tf32_kernel<<<(DFFN*DD/4)/256, 256>>>(w1, w1c, DFFN*DD/4);
    cvt_tf32_kernel<<<(DFFN*DD/4)/256, 256>>>(w2, w2c, DFFN*DD/4);

    /* LN1 -> bf16 */
    ln_kernel<true><<<NTOK, 256>>>(x, a1, c1, ln1b);
    /* Q,K,V projections (bf16 mma) -> bf16 */
    dim3 gq(DD / TBN, NTOK / TBM);
    gemm_bf<false,false,true><<<gq, 256, GSMEM>>>(ln1b, wqb, bq, nullptr, q, NTOK, DD, DD);
    gemm_bf<false,false,true><<<gq, 256, GSMEM>>>(ln1b, wkb, bk, nullptr, k, NTOK, DD, DD);
    gemm_bf<false,false,true><<<gq, 256, GSMEM>>>(ln1b, wvb, bv, nullptr, v, NTOK, DD, DD);
    /* attention (bf16 in, tf32-rounded fp32 out) */
    flash_bf16<<<dim3(SS / FBM, HH, BB), 256, FSMEM>>>(q, k, v, mask, attn);
    /* h = x + attn @ wo^T + bo  (tf32 mma) */
    gemm_tc<false,true,false,false><<<gq, 256, GSMEM>>>(attn, woc, bo, x, h, NTOK, DD, DD);
    /* LN2 (tf32 fp32 out) */
    ln_kernel<false><<<NTOK, 256>>>(h, a2, c2, ln2);
    /* ffn = relu(ln2 @ w1^T + b1)  (tf32 mma, tf32-rounded out) */
    gemm_tc<true,false,true,false><<<dim3(DFFN / TBN, NTOK / TBM), 256, GSMEM>>>(
        ln2, w1c, b1, nullptr, ffn, NTOK, DFFN, DD);
    /* out = h + ffn @ w2^T + b2  (tf32 mma) */
    gemm_tc<false,true,false,false><<<gq, 256, GSMEM>>>(ffn, w2c, b2, h, out, NTOK, DD, DFFN);
}

// round 13
// speedup vs baseline: 6.8551x; 1.3909x over previous
#include <cuda_runtime.h>
#include <cuda_bf16.h>
#include <cuda_fp16.h>
#include <math.h>
#include <stdint.h>

#define BB   4
#define SS   2048
#define DD   1024
#define HH   16
#define DKK  64
#define DFFN 4096
#define NTOK (BB*SS)
#define LNEPS 1e-6f

/* ---------------- scratch (alloc-free: __device__ globals) ---------------- */
__device__ __nv_bfloat16 g_ln1b[NTOK*DD];
__device__ __nv_bfloat16 g_qb[NTOK*DD];
__device__ __nv_bfloat16 g_kb[NTOK*DD];
__device__ __nv_bfloat16 g_vb[NTOK*DD];
__device__ __half g_attnh[NTOK*DD];
__device__ float  g_h   [NTOK*DD];
__device__ __half g_ln2h[NTOK*DD];
__device__ __half g_ffnh[(size_t)NTOK*DFFN];
__device__ __nv_bfloat16 g_wqb[DD*DD];
__device__ __nv_bfloat16 g_wkb[DD*DD];
__device__ __nv_bfloat16 g_wvb[DD*DD];
__device__ __half g_woh[DD*DD];
__device__ __half g_w1h[DFFN*DD];
__device__ __half g_w2h[DD*DFFN];

/* ---------------- helpers ------------------------------------------------- */
__device__ __forceinline__ uint32_t pack_bf16(float lo, float hi) {
    uint32_t r;
    asm("cvt.rn.bf16x2.f32 %0, %1, %2;" : "=r"(r) : "f"(hi), "f"(lo));
    return r;
}
__device__ __forceinline__ uint32_t pack_fp16(float lo, float hi) {
    uint32_t r;
    asm("cvt.rn.f16x2.f32 %0, %1, %2;" : "=r"(r) : "f"(hi), "f"(lo));
    return r;
}
__device__ __forceinline__ void mma_bf16(float* c, const uint32_t* a, const uint32_t* b) {
    asm volatile(
        "mma.sync.aligned.m16n8k16.row.col.f32.bf16.bf16.f32 "
        "{%0,%1,%2,%3}, {%4,%5,%6,%7}, {%8,%9}, {%0,%1,%2,%3};"
        : "+f"(c[0]), "+f"(c[1]), "+f"(c[2]), "+f"(c[3])
        : "r"(a[0]), "r"(a[1]), "r"(a[2]), "r"(a[3]), "r"(b[0]), "r"(b[1]));
}
__device__ __forceinline__ void mma_fp16(float* c, const uint32_t* a, const uint32_t* b) {
    asm volatile(
        "mma.sync.aligned.m16n8k16.row.col.f32.f16.f16.f32 "
        "{%0,%1,%2,%3}, {%4,%5,%6,%7}, {%8,%9}, {%0,%1,%2,%3};"
        : "+f"(c[0]), "+f"(c[1]), "+f"(c[2]), "+f"(c[3])
        : "r"(a[0]), "r"(a[1]), "r"(a[2]), "r"(a[3]), "r"(b[0]), "r"(b[1]));
}
__device__ __forceinline__ void cp16s(uint32_t saddr, const void* g) {
    asm volatile("cp.async.cg.shared.global [%0], [%1], 16;" :: "r"(saddr), "l"(g));
}
__device__ __forceinline__ uint32_t smem_u32(const void* p) {
    return (uint32_t)__cvta_generic_to_shared(p);
}
__device__ __forceinline__ void ldsm4(uint32_t* r, uint32_t addr) {
    asm volatile("ldmatrix.sync.aligned.m8n8.x4.shared.b16 {%0,%1,%2,%3}, [%4];"
        : "=r"(r[0]), "=r"(r[1]), "=r"(r[2]), "=r"(r[3]) : "r"(addr));
}
__device__ __forceinline__ void ldsm4t(uint32_t* r, uint32_t addr) {
    asm volatile("ldmatrix.sync.aligned.m8n8.x4.trans.shared.b16 {%0,%1,%2,%3}, [%4];"
        : "=r"(r[0]), "=r"(r[1]), "=r"(r[2]), "=r"(r[3]) : "r"(addr));
}

/* ---------------- weight pre-rounding ------------------------------------- */
__global__ void cvt_bf16_kernel(const float* __restrict__ src,
                                __nv_bfloat16* __restrict__ dst, int n4) {
    int i = blockIdx.x * 256 + threadIdx.x;
    if (i < n4) {
        float4 v = ((const float4*)src)[i];
        uint2 o;
        o.x = pack_bf16(v.x, v.y);
        o.y = pack_bf16(v.z, v.w);
        ((uint2*)dst)[i] = o;
    }
}
__global__ void cvt_fp16_kernel(const float* __restrict__ src,
                                __half* __restrict__ dst, int n4) {
    int i = blockIdx.x * 256 + threadIdx.x;
    if (i < n4) {
        float4 v = ((const float4*)src)[i];
        uint2 o;
        o.x = pack_fp16(v.x, v.y);
        o.y = pack_fp16(v.z, v.w);
        ((uint2*)dst)[i] = o;
    }
}

/* ---------------- LayerNorm: OUTMODE 1=bf16, 2=fp16 ------------------------ */
template<int OUTMODE>
__global__ void ln_kernel(const float* __restrict__ x,
                          const float* __restrict__ ap,
                          const float* __restrict__ cp,
                          void* __restrict__ y) {
    __shared__ float sred[16];
    int row = blockIdx.x;
    int tid = threadIdx.x;
    const float4 v = ((const float4*)(x + (size_t)row*DD))[tid];
    float s  = v.x + v.y + v.z + v.w;
    float sq = v.x*v.x + v.y*v.y + v.z*v.z + v.w*v.w;
    #pragma unroll
    for (int off = 16; off > 0; off >>= 1) {
        s  += __shfl_xor_sync(0xffffffffu, s,  off);
        sq += __shfl_xor_sync(0xffffffffu, sq, off);
    }
    int warp = tid >> 5, lane = tid & 31;
    if (lane == 0) { sred[warp] = s; sred[warp + 8] = sq; }
    __syncthreads();
    float st = 0.f, sqt = 0.f;
    #pragma unroll
    for (int i = 0; i < 8; i++) { st += sred[i]; sqt += sred[i + 8]; }
    float mean = st * (1.0f / DD);
    float var  = (sqt - (float)DD * mean * mean) * (1.0f / (DD - 1));
    float stdv = sqrtf(fmaxf(var, 0.f));
    float inv  = ap[0] / (stdv + LNEPS);
    float beta = cp[0];
    float o0 = (v.x - mean) * inv + beta;
    float o1 = (v.y - mean) * inv + beta;
    float o2 = (v.z - mean) * inv + beta;
    float o3 = (v.w - mean) * inv + beta;
    uint2 o;
    if (OUTMODE == 1) { o.x = pack_bf16(o0, o1); o.y = pack_bf16(o2, o3); }
    else              { o.x = pack_fp16(o0, o1); o.y = pack_fp16(o2, o3); }
    ((uint2*)((uint16_t*)y + (size_t)row*DD))[tid] = o;
}

/* ========== 16-bit TC NT GEMM: 128x256 CTA, TBK=64 (128B rows) ============ */
/* FP16MMA selects f16 vs bf16 mma; fragment layout identical (b16 ldmatrix). */
/* OUTMODE: 0=fp32, 1=bf16, 2=fp16.                                           */
#define TBM 128
#define TBN 256
#define A_STG 16384
#define B_STG 32768
#define GSMEM (2 * (A_STG + B_STG))   /* 96 KB */

template<bool RELU, bool RES, bool FP16MMA, int OUTMODE>
__global__ void __launch_bounds__(256)
gemm16(const uint16_t* __restrict__ A, const uint16_t* __restrict__ Bw,
       const float* __restrict__ bias, const float* __restrict__ res,
       void* __restrict__ Cv, int M, int N, int K) {
    extern __shared__ __align__(1024) float sm[];
    const int tid = threadIdx.x;
    const int warp = tid >> 5, lane = tid & 31;
    const int g = lane >> 2, t = lane & 3;
    const int wm = warp & 1, wn = warp >> 1;
    const int bm = blockIdx.y, bn = blockIdx.x;

    const uint32_t smbase = smem_u32(sm);
    const uint32_t aoff[2] = { smbase,               smbase + A_STG };
    const uint32_t boff[2] = { smbase + 2 * A_STG,   smbase + 2 * A_STG + B_STG };

    const uint16_t* Ab = A  + (size_t)(bm * TBM) * K;
    const uint16_t* Bb = Bw + (size_t)(bn * TBN) * K;
    const int ntiles = K / 64;

    float acc[4][8][4] = {};

    const int aR = lane & 15;                        /* A-frag: row in m16   */
    const int aH = lane >> 4;                        /* A-frag: k8 half      */
    const int bR = ((lane >> 4) << 3) + (lane & 7);  /* B-frag: row in n16   */
    const int bH = (lane >> 3) & 1;                  /* B-frag: k8 half      */

    #define BSTAGE(buf, k0)                                                    \
    {                                                                          \
        _Pragma("unroll")                                                      \
        for (int i = 0; i < 4; i++) {                                          \
            int s = tid + i * 256;                                             \
            int r = s >> 3, c = s & 7;                                         \
            cp16s(aoff[buf] + r * 128 + (((c ^ (r & 7)) << 4)),                \
                  Ab + (size_t)r * K + (k0) + c * 8);                          \
        }                                                                      \
        _Pragma("unroll")                                                      \
        for (int i = 0; i < 8; i++) {                                          \
            int s = tid + i * 256;                                             \
            int r = s >> 3, c = s & 7;                                         \
            cp16s(boff[buf] + r * 128 + (((c ^ (r & 7)) << 4)),                \
                  Bb + (size_t)r * K + (k0) + c * 8);                          \
        }                                                                      \
    }

    BSTAGE(0, 0);
    asm volatile("cp.async.commit_group;");

    for (int kt = 0; kt < ntiles; kt++) {
        if (kt + 1 < ntiles) {
            BSTAGE((kt + 1) & 1, (kt + 1) * 64);
            asm volatile("cp.async.commit_group;");
            asm volatile("cp.async.wait_group 1;");
        } else {
            asm volatile("cp.async.commit_group;");
            asm volatile("cp.async.wait_group 0;");
        }
        __syncthreads();
        const uint32_t ab = aoff[kt & 1], bb = boff[kt & 1];
        #pragma unroll
        for (int ks = 0; ks < 4; ks++) {
            uint32_t af[4][4], bf[4][4];
            #pragma unroll
            for (int mt = 0; mt < 4; mt++) {
                int R = wm * 64 + mt * 16 + aR;
                ldsm4(af[mt], ab + R * 128 + (((ks * 2 + aH) ^ (R & 7)) << 4));
            }
            #pragma unroll
            for (int jp = 0; jp < 4; jp++) {
                int R = wn * 64 + jp * 16 + bR;
                ldsm4(bf[jp], bb + R * 128 + (((ks * 2 + bH) ^ (R & 7)) << 4));
            }
            #pragma unroll
            for (int mt = 0; mt < 4; mt++)
                #pragma unroll
                for (int nt = 0; nt < 8; nt++) {
                    if (FP16MMA) mma_fp16(acc[mt][nt], af[mt], &bf[nt >> 1][(nt & 1) * 2]);
                    else         mma_bf16(acc[mt][nt], af[mt], &bf[nt >> 1][(nt & 1) * 2]);
                }
        }
        __syncthreads();
    }
    #undef BSTAGE

    /* epilogue */
    #pragma unroll
    for (int mt = 0; mt < 4; mt++) {
        #pragma unroll
        for (int nt = 0; nt < 8; nt++) {
            int col = bn * TBN + wn * 64 + nt * 8 + t * 2;
            float bx = bias[col], by = bias[col + 1];
            #pragma unroll
            for (int half = 0; half < 2; half++) {
                size_t row = (size_t)(bm * TBM + wm * 64 + mt * 16 + g + half * 8);
                float ox = acc[mt][nt][half * 2 + 0] + bx;
                float oy = acc[mt][nt][half * 2 + 1] + by;
                if (RELU) { ox = fmaxf(ox, 0.f); oy = fmaxf(oy, 0.f); }
                if (RES) {
                    float2 r2 = *(const float2*)(res + row * N + col);
                    ox += r2.x; oy += r2.y;
                }
                if (OUTMODE == 0) {
                    *(float2*)((float*)Cv + row * N + col) = make_float2(ox, oy);
                } else if (OUTMODE == 1) {
                    *(uint32_t*)((uint16_t*)Cv + row * N + col) = pack_bf16(ox, oy);
                } else {
                    *(uint32_t*)((uint16_t*)Cv + row * N + col) = pack_fp16(ox, oy);
                }
            }
        }
    }
}

/* ================= bf16 flash attention (fp16 output) ===================== */
#define FBM 128
#define FBN 64
#define FNT (SS / FBN)
#define FQP   0
#define FK    16384
#define FV    (16384 + 2 * 8192)
#define FSMEM (16384 + 4 * 8192)

__global__ void __launch_bounds__(256, 1)
flash_bf16(const __nv_bfloat16* __restrict__ Q,
           const __nv_bfloat16* __restrict__ Kg,
           const __nv_bfloat16* __restrict__ Vg,
           const int* __restrict__ mask, __half* __restrict__ O) {
    extern __shared__ __align__(1024) char fsm[];
    const uint32_t sb = smem_u32(fsm);
    const uint32_t qp = sb + FQP;
    const uint32_t koff[2] = { sb + FK, sb + FK + 8192 };
    const uint32_t voff[2] = { sb + FV, sb + FV + 8192 };

    const int qt = blockIdx.x, h = blockIdx.y, b = blockIdx.z;
    const int tid = threadIdx.x;
    const int w = tid >> 5, lane = tid & 31, g = lane >> 2, t = lane & 3;

    const __nv_bfloat16* qb = Q + (size_t)(b * SS + qt * FBM) * DD + h * DKK;
    #pragma unroll
    for (int i = 0; i < 4; i++) {
        int s = tid + i * 256;
        int r = s >> 3, c = s & 7;
        *(uint4*)(fsm + FQP + r * 128 + ((c ^ (r & 7)) << 4)) =
            *(const uint4*)(qb + (size_t)r * DD + c * 8);
    }
    __syncthreads();
    uint32_t qf[4][4];
    {
        const int R = w * 16 + (lane & 15);
        const int hh = lane >> 4;
        #pragma unroll
        for (int ks = 0; ks < 4; ks++)
            ldsm4(qf[ks], qp + R * 128 + (((ks * 2 + hh) ^ (R & 7)) << 4));
    }
    __syncthreads();

    const __nv_bfloat16* kb = Kg + (size_t)(b * SS) * DD + h * DKK;
    const __nv_bfloat16* vb = Vg + (size_t)(b * SS) * DD + h * DKK;
    #define KVSTAGE(buf, kt)                                                   \
    {                                                                          \
        const __nv_bfloat16* kg = kb + (size_t)((kt) * FBN) * DD;              \
        const __nv_bfloat16* vg = vb + (size_t)((kt) * FBN) * DD;              \
        _Pragma("unroll")                                                      \
        for (int i = 0; i < 2; i++) {                                          \
            int s = tid + i * 256;                                             \
            int r = s >> 3, c = s & 7;                                         \
            cp16s(koff[buf] + r * 128 + ((c ^ (r & 7)) << 4),                  \
                  kg + (size_t)r * DD + c * 8);                                \
            cp16s(voff[buf] + r * 128 + ((c ^ (r & 7)) << 4),                  \
                  vg + (size_t)r * DD + c * 8);                                \
        }                                                                      \
    }
    KVSTAGE(0, 0);
    asm volatile("cp.async.commit_group;");

    float oacc[8][4] = {};
    float mrow0 = -1e30f, mrow1 = -1e30f, lrow0 = 0.f, lrow1 = 0.f;
    const int* mp = mask + b * SS;

    const int kbR = (lane & 7) + ((lane >> 4) << 3);
    const int kbH = (lane >> 3) & 1;
    const int vbR = (lane & 7) + (((lane >> 3) & 1) << 3);
    const int vbH = lane >> 4;
    const int paR = lane & 15, paH = lane >> 4;

    for (int kt = 0; kt < FNT; kt++) {
        if (kt + 1 < FNT) {
            KVSTAGE((kt + 1) & 1, kt + 1);
            asm volatile("cp.async.commit_group;");
            asm volatile("cp.async.wait_group 1;");
        } else {
            asm volatile("cp.async.commit_group;");
            asm volatile("cp.async.wait_group 0;");
        }
        __syncthreads();
        const uint32_t kbuf = koff[kt & 1], vbuf = voff[kt & 1];

        float sacc[8][4] = {};
        #pragma unroll
        for (int ks = 0; ks < 4; ks++) {
            #pragma unroll
            for (int np = 0; np < 4; np++) {
                uint32_t bf[4];
                int R = np * 16 + kbR;
                ldsm4(bf, kbuf + R * 128 + (((ks * 2 + kbH) ^ (R & 7)) << 4));
                mma_bf16(sacc[np * 2 + 0], qf[ks], &bf[0]);
                mma_bf16(sacc[np * 2 + 1], qf[ks], &bf[2]);
            }
        }
        #pragma unroll
        for (int nt = 0; nt < 8; nt++) {
            int mj0 = __ldg(mp + kt * FBN + nt * 8 + 2 * t);
            int mj1 = __ldg(mp + kt * FBN + nt * 8 + 2 * t + 1);
            sacc[nt][0] = mj0 ? sacc[nt][0] * 0.125f : -1e9f;
            sacc[nt][1] = mj1 ? sacc[nt][1] * 0.125f : -1e9f;
            sacc[nt][2] = mj0 ? sacc[nt][2] * 0.125f : -1e9f;
            sacc[nt][3] = mj1 ? sacc[nt][3] * 0.125f : -1e9f;
        }
        float tm0 = -1e30f, tm1 = -1e30f;
        #pragma unroll
        for (int nt = 0; nt < 8; nt++) {
            tm0 = fmaxf(tm0, fmaxf(sacc[nt][0], sacc[nt][1]));
            tm1 = fmaxf(tm1, fmaxf(sacc[nt][2], sacc[nt][3]));
        }
        tm0 = fmaxf(tm0, __shfl_xor_sync(0xffffffffu, tm0, 1));
        tm0 = fmaxf(tm0, __shfl_xor_sync(0xffffffffu, tm0, 2));
        tm1 = fmaxf(tm1, __shfl_xor_sync(0xffffffffu, tm1, 1));
        tm1 = fmaxf(tm1, __shfl_xor_sync(0xffffffffu, tm1, 2));
        float mn0 = fmaxf(mrow0, tm0), mn1 = fmaxf(mrow1, tm1);
        float cr0 = __expf(mrow0 - mn0), cr1 = __expf(mrow1 - mn1);
        float sum0 = 0.f, sum1 = 0.f;
        #pragma unroll
        for (int nt = 0; nt < 8; nt++) {
            sacc[nt][0] = __expf(sacc[nt][0] - mn0);
            sacc[nt][1] = __expf(sacc[nt][1] - mn0);
            sacc[nt][2] = __expf(sacc[nt][2] - mn1);
            sacc[nt][3] = __expf(sacc[nt][3] - mn1);
            sum0 += sacc[nt][0] + sacc[nt][1];
            sum1 += sacc[nt][2] + sacc[nt][3];
        }
        sum0 += __shfl_xor_sync(0xffffffffu, sum0, 1);
        sum0 += __shfl_xor_sync(0xffffffffu, sum0, 2);
        sum1 += __shfl_xor_sync(0xffffffffu, sum1, 1);
        sum1 += __shfl_xor_sync(0xffffffffu, sum1, 2);
        lrow0 = lrow0 * cr0 + sum0; mrow0 = mn0;
        lrow1 = lrow1 * cr1 + sum1; mrow1 = mn1;
        #pragma unroll
        for (int nt = 0; nt < 8; nt++) {
            oacc[nt][0] *= cr0; oacc[nt][1] *= cr0;
            oacc[nt][2] *= cr1; oacc[nt][3] *= cr1;
        }
        {
            const uint32_t pr0 = qp + (w * 16 + g) * 128;
            const uint32_t pr1 = qp + (w * 16 + g + 8) * 128;
            #pragma unroll
            for (int nt = 0; nt < 8; nt++) {
                uint32_t off = ((nt ^ g) << 4) + t * 4;
                *(uint32_t*)(fsm + (pr0 + off - sb)) = pack_bf16(sacc[nt][0], sacc[nt][1]);
                *(uint32_t*)(fsm + (pr1 + off - sb)) = pack_bf16(sacc[nt][2], sacc[nt][3]);
            }
        }
        __syncwarp();
        #pragma unroll
        for (int ks = 0; ks < 4; ks++) {
            uint32_t pf[4];
            {
                int R = w * 16 + paR;
                ldsm4(pf, qp + R * 128 + (((ks * 2 + paH) ^ (R & 7)) << 4));
            }
            #pragma unroll
            for (int np = 0; np < 4; np++) {
                uint32_t bv[4];
                int R = ks * 16 + vbR;
                ldsm4t(bv, vbuf + R * 128 + (((np * 2 + vbH) ^ (R & 7)) << 4));
                mma_bf16(oacc[np * 2 + 0], pf, &bv[0]);
                mma_bf16(oacc[np * 2 + 1], pf, &bv[2]);
            }
        }
        __syncthreads();
    }
    #undef KVSTAGE

    /* epilogue: normalize, store fp16 (feeds fp16 wo GEMM) */
    float inv0 = 1.f / lrow0, inv1 = 1.f / lrow1;
    __half* ob = O + (size_t)(b * SS + qt * FBM) * DD + h * DKK;
    int r0 = w * 16 + g;
    #pragma unroll
    for (int nt = 0; nt < 8; nt++) {
        int col = nt * 8 + 2 * t;
        *(uint32_t*)(ob + (size_t)r0 * DD + col) =
            pack_fp16(oacc[nt][0] * inv0, oacc[nt][1] * inv0);
        *(uint32_t*)(ob + (size_t)(r0 + 8) * DD + col) =
            pack_fp16(oacc[nt][2] * inv1, oacc[nt][3] * inv1);
    }
}

/* ---------------- host orchestration (graph-capturable) ------------------- */
extern "C" void kernel_launch(void* const* d_in, const int* in_sizes, int n_in,
                              void* d_out, int out_size) {
    (void)in_sizes; (void)n_in; (void)out_size;
    const float* x    = (const float*)d_in[0];
    const int*   mask = (const int*)  d_in[1];
    const float* wq   = (const float*)d_in[2];
    const float* bq   = (const float*)d_in[3];
    const float* wk   = (const float*)d_in[4];
    const float* bk   = (const float*)d_in[5];
    const float* wv   = (const float*)d_in[6];
    const float* bv   = (const float*)d_in[7];
    const float* wo   = (const float*)d_in[8];
    const float* bo   = (const float*)d_in[9];
    const float* w1   = (const float*)d_in[10];
    const float* b1   = (const float*)d_in[11];
    const float* w2   = (const float*)d_in[12];
    const float* b2   = (const float*)d_in[13];
    const float* a1   = (const float*)d_in[14];
    const float* c1   = (const float*)d_in[15];
    const float* a2   = (const float*)d_in[16];
    const float* c2   = (const float*)d_in[17];
    float* out = (float*)d_out;

    float *h;
    __nv_bfloat16 *ln1b, *q, *k, *v, *wqb, *wkb, *wvb;
    __half *attnh, *ln2h, *ffnh, *woh, *w1h, *w2h;
    cudaGetSymbolAddress((void**)&ln1b,  g_ln1b);
    cudaGetSymbolAddress((void**)&q,     g_qb);
    cudaGetSymbolAddress((void**)&k,     g_kb);
    cudaGetSymbolAddress((void**)&v,     g_vb);
    cudaGetSymbolAddress((void**)&attnh, g_attnh);
    cudaGetSymbolAddress((void**)&h,     g_h);
    cudaGetSymbolAddress((void**)&ln2h,  g_ln2h);
    cudaGetSymbolAddress((void**)&ffnh,  g_ffnh);
    cudaGetSymbolAddress((void**)&wqb,   g_wqb);
    cudaGetSymbolAddress((void**)&wkb,   g_wkb);
    cudaGetSymbolAddress((void**)&wvb,   g_wvb);
    cudaGetSymbolAddress((void**)&woh,   g_woh);
    cudaGetSymbolAddress((void**)&w1h,   g_w1h);
    cudaGetSymbolAddress((void**)&w2h,   g_w2h);

    cudaFuncSetAttribute(flash_bf16,
                         cudaFuncAttributeMaxDynamicSharedMemorySize, FSMEM);
    cudaFuncSetAttribute(gemm16<false,false,false,1>,
                         cudaFuncAttributeMaxDynamicSharedMemorySize, GSMEM);
    cudaFuncSetAttribute(gemm16<false,true,true,0>,
                         cudaFuncAttributeMaxDynamicSharedMemorySize, GSMEM);
    cudaFuncSetAttribute(gemm16<true,false,true,2>,
                         cudaFuncAttributeMaxDynamicSharedMemorySize, GSMEM);

    /* weight pre-rounding: QKV -> bf16; wo/w1/w2 -> fp16 */
    cvt_bf16_kernel<<<(DD*DD/4)/256,   256>>>(wq, wqb, DD*DD/4);
    cvt_bf16_kernel<<<(DD*DD/4)/256,   256>>>(wk, wkb, DD*DD/4);
    cvt_bf16_kernel<<<(DD*DD/4)/256,   256>>>(wv, wvb, DD*DD/4);
    cvt_fp16_kernel<<<(DD*DD/4)/256,   256>>>(wo, woh, DD*DD/4);
    cvt_fp16_kernel<<<(DFFN*DD/4)/256, 256>>>(w1, w1h, DFFN*DD/4);
    cvt_fp16_kernel<<<(DFFN*DD/4)/256, 256>>>(w2, w2h, DFFN*DD/4);

    /* LN1 -> bf16 */
    ln_kernel<1><<<NTOK, 256>>>(x, a1, c1, ln1b);
    /* Q,K,V projections (bf16 mma) -> bf16 */
    dim3 gq(DD / TBN, NTOK / TBM);
    gemm16<false,false,false,1><<<gq, 256, GSMEM>>>(
        (const uint16_t*)ln1b, (const uint16_t*)wqb, bq, nullptr, q, NTOK, DD, DD);
    gemm16<false,false,false,1><<<gq, 256, GSMEM>>>(
        (const uint16_t*)ln1b, (const uint16_t*)wkb, bk, nullptr, k, NTOK, DD, DD);
    gemm16<false,false,false,1><<<gq, 256, GSMEM>>>(
        (const uint16_t*)ln1b, (const uint16_t*)wvb, bv, nullptr, v, NTOK, DD, DD);
    /* attention (bf16 in, fp16 out) */
    flash_bf16<<<dim3(SS / FBM, HH, BB), 256, FSMEM>>>(q, k, v, mask, attnh);
    /* h = x + attn @ wo^T + bo  (fp16 mma, fp32 out) */
    gemm16<false,true,true,0><<<gq, 256, GSMEM>>>(
        (const uint16_t*)attnh, (const uint16_t*)woh, bo, x, h, NTOK, DD, DD);
    /* LN2 -> fp16 */
    ln_kernel<2><<<NTOK, 256>>>(h, a2, c2, ln2h);
    /* ffn = relu(ln2 @ w1^T + b1)  (fp16 mma, fp16 out) */
    gemm16<true,false,true,2><<<dim3(DFFN / TBN, NTOK / TBM), 256, GSMEM>>>(
        (const uint16_t*)ln2h, (const uint16_t*)w1h, b1, nullptr, ffnh, NTOK, DFFN, DD);
    /* out = h + ffn @ w2^T + b2  (fp16 mma, fp32 out) */
    gemm16<false,true,true,0><<<gq, 256, GSMEM>>>(
        (const uint16_t*)ffnh, (const uint16_t*)w2h, b2, h, out, NTOK, DD, DFFN);
}

// round 14
// speedup vs baseline: 7.5015x; 1.0943x over previous
#include <cuda_runtime.h>
#include <cuda_bf16.h>
#include <cuda_fp16.h>
#include <math.h>
#include <stdint.h>

#define BB   4
#define SS   2048
#define DD   1024
#define HH   16
#define DKK  64
#define DFFN 4096
#define NTOK (BB*SS)
#define QSTR (3*DD)           /* packed qkv row stride */
#define LNEPS 1e-6f

/* ---------------- scratch (alloc-free: __device__ globals) ---------------- */
__device__ __nv_bfloat16 g_ln1b[NTOK*DD];
__device__ __nv_bfloat16 g_qkvb[(size_t)NTOK*QSTR];
__device__ __half g_attnh[NTOK*DD];
__device__ float  g_h   [NTOK*DD];
__device__ __half g_ln2h[NTOK*DD];
__device__ __half g_ffnh[(size_t)NTOK*DFFN];
__device__ __nv_bfloat16 g_wqkvb[3*DD*DD];
__device__ float  g_bqkv[3*DD];
__device__ __half g_woh[DD*DD];
__device__ __half g_w1h[DFFN*DD];
__device__ __half g_w2h[DD*DFFN];

/* ---------------- helpers ------------------------------------------------- */
__device__ __forceinline__ uint32_t pack_bf16(float lo, float hi) {
    uint32_t r;
    asm("cvt.rn.bf16x2.f32 %0, %1, %2;" : "=r"(r) : "f"(hi), "f"(lo));
    return r;
}
__device__ __forceinline__ uint32_t pack_fp16(float lo, float hi) {
    uint32_t r;
    asm("cvt.rn.f16x2.f32 %0, %1, %2;" : "=r"(r) : "f"(hi), "f"(lo));
    return r;
}
__device__ __forceinline__ float ex2(float x) {
    float y;
    asm("ex2.approx.f32 %0, %1;" : "=f"(y) : "f"(x));
    return y;
}
__device__ __forceinline__ void mma_bf16(float* c, const uint32_t* a, const uint32_t* b) {
    asm volatile(
        "mma.sync.aligned.m16n8k16.row.col.f32.bf16.bf16.f32 "
        "{%0,%1,%2,%3}, {%4,%5,%6,%7}, {%8,%9}, {%0,%1,%2,%3};"
        : "+f"(c[0]), "+f"(c[1]), "+f"(c[2]), "+f"(c[3])
        : "r"(a[0]), "r"(a[1]), "r"(a[2]), "r"(a[3]), "r"(b[0]), "r"(b[1]));
}
__device__ __forceinline__ void mma_fp16(float* c, const uint32_t* a, const uint32_t* b) {
    asm volatile(
        "mma.sync.aligned.m16n8k16.row.col.f32.f16.f16.f32 "
        "{%0,%1,%2,%3}, {%4,%5,%6,%7}, {%8,%9}, {%0,%1,%2,%3};"
        : "+f"(c[0]), "+f"(c[1]), "+f"(c[2]), "+f"(c[3])
        : "r"(a[0]), "r"(a[1]), "r"(a[2]), "r"(a[3]), "r"(b[0]), "r"(b[1]));
}
__device__ __forceinline__ void cp16s(uint32_t saddr, const void* g) {
    asm volatile("cp.async.cg.shared.global [%0], [%1], 16;" :: "r"(saddr), "l"(g));
}
__device__ __forceinline__ uint32_t smem_u32(const void* p) {
    return (uint32_t)__cvta_generic_to_shared(p);
}
__device__ __forceinline__ void ldsm4(uint32_t* r, uint32_t addr) {
    asm volatile("ldmatrix.sync.aligned.m8n8.x4.shared.b16 {%0,%1,%2,%3}, [%4];"
        : "=r"(r[0]), "=r"(r[1]), "=r"(r[2]), "=r"(r[3]) : "r"(addr));
}
__device__ __forceinline__ void ldsm4t(uint32_t* r, uint32_t addr) {
    asm volatile("ldmatrix.sync.aligned.m8n8.x4.trans.shared.b16 {%0,%1,%2,%3}, [%4];"
        : "=r"(r[0]), "=r"(r[1]), "=r"(r[2]), "=r"(r[3]) : "r"(addr));
}

/* ---------------- weight pre-rounding ------------------------------------- */
__global__ void cvt_bf16_kernel(const float* __restrict__ src,
                                __nv_bfloat16* __restrict__ dst, int n4) {
    int i = blockIdx.x * 256 + threadIdx.x;
    if (i < n4) {
        float4 v = ((const float4*)src)[i];
        uint2 o;
        o.x = pack_bf16(v.x, v.y);
        o.y = pack_bf16(v.z, v.w);
        ((uint2*)dst)[i] = o;
    }
}
__global__ void cvt_fp16_kernel(const float* __restrict__ src,
                                __half* __restrict__ dst, int n4) {
    int i = blockIdx.x * 256 + threadIdx.x;
    if (i < n4) {
        float4 v = ((const float4*)src)[i];
        uint2 o;
        o.x = pack_fp16(v.x, v.y);
        o.y = pack_fp16(v.z, v.w);
        ((uint2*)dst)[i] = o;
    }
}

/* ---------------- LayerNorm: OUTMODE 1=bf16, 2=fp16 ------------------------ */
template<int OUTMODE>
__global__ void ln_kernel(const float* __restrict__ x,
                          const float* __restrict__ ap,
                          const float* __restrict__ cp,
                          void* __restrict__ y) {
    __shared__ float sred[16];
    int row = blockIdx.x;
    int tid = threadIdx.x;
    const float4 v = ((const float4*)(x + (size_t)row*DD))[tid];
    float s  = v.x + v.y + v.z + v.w;
    float sq = v.x*v.x + v.y*v.y + v.z*v.z + v.w*v.w;
    #pragma unroll
    for (int off = 16; off > 0; off >>= 1) {
        s  += __shfl_xor_sync(0xffffffffu, s,  off);
        sq += __shfl_xor_sync(0xffffffffu, sq, off);
    }
    int warp = tid >> 5, lane = tid & 31;
    if (lane == 0) { sred[warp] = s; sred[warp + 8] = sq; }
    __syncthreads();
    float st = 0.f, sqt = 0.f;
    #pragma unroll
    for (int i = 0; i < 8; i++) { st += sred[i]; sqt += sred[i + 8]; }
    float mean = st * (1.0f / DD);
    float var  = (sqt - (float)DD * mean * mean) * (1.0f / (DD - 1));
    float stdv = sqrtf(fmaxf(var, 0.f));
    float inv  = ap[0] / (stdv + LNEPS);
    float beta = cp[0];
    float o0 = (v.x - mean) * inv + beta;
    float o1 = (v.y - mean) * inv + beta;
    float o2 = (v.z - mean) * inv + beta;
    float o3 = (v.w - mean) * inv + beta;
    uint2 o;
    if (OUTMODE == 1) { o.x = pack_bf16(o0, o1); o.y = pack_bf16(o2, o3); }
    else              { o.x = pack_fp16(o0, o1); o.y = pack_fp16(o2, o3); }
    ((uint2*)((uint16_t*)y + (size_t)row*DD))[tid] = o;
}

/* ========== 16-bit TC NT GEMM: 128x256 CTA, TBK=64 (128B rows) ============ */
#define TBM 128
#define TBN 256
#define A_STG 16384
#define B_STG 32768
#define GSMEM (2 * (A_STG + B_STG))   /* 96 KB */

template<bool RELU, bool RES, bool FP16MMA, int OUTMODE>
__global__ void __launch_bounds__(256)
gemm16(const uint16_t* __restrict__ A, const uint16_t* __restrict__ Bw,
       const float* __restrict__ bias, const float* __restrict__ res,
       void* __restrict__ Cv, int M, int N, int K) {
    extern __shared__ __align__(1024) float sm[];
    const int tid = threadIdx.x;
    const int warp = tid >> 5, lane = tid & 31;
    const int g = lane >> 2, t = lane & 3;
    const int wm = warp & 1, wn = warp >> 1;
    const int bm = blockIdx.y, bn = blockIdx.x;

    const uint32_t smbase = smem_u32(sm);
    const uint32_t aoff[2] = { smbase,               smbase + A_STG };
    const uint32_t boff[2] = { smbase + 2 * A_STG,   smbase + 2 * A_STG + B_STG };

    const uint16_t* Ab = A  + (size_t)(bm * TBM) * K;
    const uint16_t* Bb = Bw + (size_t)(bn * TBN) * K;
    const int ntiles = K / 64;

    float acc[4][8][4] = {};

    const int aR = lane & 15;
    const int aH = lane >> 4;
    const int bR = ((lane >> 4) << 3) + (lane & 7);
    const int bH = (lane >> 3) & 1;

    #define BSTAGE(buf, k0)                                                    \
    {                                                                          \
        _Pragma("unroll")                                                      \
        for (int i = 0; i < 4; i++) {                                          \
            int s = tid + i * 256;                                             \
            int r = s >> 3, c = s & 7;                                         \
            cp16s(aoff[buf] + r * 128 + (((c ^ (r & 7)) << 4)),                \
                  Ab + (size_t)r * K + (k0) + c * 8);                          \
        }                                                                      \
        _Pragma("unroll")                                                      \
        for (int i = 0; i < 8; i++) {                                          \
            int s = tid + i * 256;                                             \
            int r = s >> 3, c = s & 7;                                         \
            cp16s(boff[buf] + r * 128 + (((c ^ (r & 7)) << 4)),                \
                  Bb + (size_t)r * K + (k0) + c * 8);                          \
        }                                                                      \
    }

    BSTAGE(0, 0);
    asm volatile("cp.async.commit_group;");

    for (int kt = 0; kt < ntiles; kt++) {
        if (kt + 1 < ntiles) {
            BSTAGE((kt + 1) & 1, (kt + 1) * 64);
            asm volatile("cp.async.commit_group;");
            asm volatile("cp.async.wait_group 1;");
        } else {
            asm volatile("cp.async.commit_group;");
            asm volatile("cp.async.wait_group 0;");
        }
        __syncthreads();
        const uint32_t ab = aoff[kt & 1], bb = boff[kt & 1];
        #pragma unroll
        for (int ks = 0; ks < 4; ks++) {
            uint32_t af[4][4], bf[4][4];
            #pragma unroll
            for (int mt = 0; mt < 4; mt++) {
                int R = wm * 64 + mt * 16 + aR;
                ldsm4(af[mt], ab + R * 128 + (((ks * 2 + aH) ^ (R & 7)) << 4));
            }
            #pragma unroll
            for (int jp = 0; jp < 4; jp++) {
                int R = wn * 64 + jp * 16 + bR;
                ldsm4(bf[jp], bb + R * 128 + (((ks * 2 + bH) ^ (R & 7)) << 4));
            }
            #pragma unroll
            for (int mt = 0; mt < 4; mt++)
                #pragma unroll
                for (int nt = 0; nt < 8; nt++) {
                    if (FP16MMA) mma_fp16(acc[mt][nt], af[mt], &bf[nt >> 1][(nt & 1) * 2]);
                    else         mma_bf16(acc[mt][nt], af[mt], &bf[nt >> 1][(nt & 1) * 2]);
                }
        }
        __syncthreads();
    }
    #undef BSTAGE

    /* epilogue */
    #pragma unroll
    for (int mt = 0; mt < 4; mt++) {
        #pragma unroll
        for (int nt = 0; nt < 8; nt++) {
            int col = bn * TBN + wn * 64 + nt * 8 + t * 2;
            float bx = bias[col], by = bias[col + 1];
            #pragma unroll
            for (int half = 0; half < 2; half++) {
                size_t row = (size_t)(bm * TBM + wm * 64 + mt * 16 + g + half * 8);
                float ox = acc[mt][nt][half * 2 + 0] + bx;
                float oy = acc[mt][nt][half * 2 + 1] + by;
                if (RELU) { ox = fmaxf(ox, 0.f); oy = fmaxf(oy, 0.f); }
                if (RES) {
                    float2 r2 = *(const float2*)(res + row * N + col);
                    ox += r2.x; oy += r2.y;
                }
                if (OUTMODE == 0) {
                    *(float2*)((float*)Cv + row * N + col) = make_float2(ox, oy);
                } else if (OUTMODE == 1) {
                    *(uint32_t*)((uint16_t*)Cv + row * N + col) = pack_bf16(ox, oy);
                } else {
                    *(uint32_t*)((uint16_t*)Cv + row * N + col) = pack_fp16(ox, oy);
                }
            }
        }
    }
}

/* ================= bf16 flash attention (packed QKV, 4-stage KV) ========== */
/* exp2-domain softmax: scale = 0.125*log2e, mask -> -1e9*log2e.              */
#define FBM 128
#define FBN 64
#define FNT (SS / FBN)
#define FQP   0
#define FK    16384
#define FV    (16384 + 4 * 8192)
#define FSMEM (16384 + 8 * 8192)     /* 80 KB */
#define SCALE2 0.180336880f           /* 0.125 * log2(e) */
#define MASK2  -1.442695040e9f        /* -1e9 * log2(e)  */

__global__ void __launch_bounds__(256, 2)
flash_bf16(const __nv_bfloat16* __restrict__ QKV,
           const int* __restrict__ mask, __half* __restrict__ O) {
    extern __shared__ __align__(1024) char fsm[];
    const uint32_t sb = smem_u32(fsm);
    const uint32_t qp = sb + FQP;
    const uint32_t koff[4] = { sb + FK,          sb + FK + 8192,
                               sb + FK + 16384,  sb + FK + 24576 };
    const uint32_t voff[4] = { sb + FV,          sb + FV + 8192,
                               sb + FV + 16384,  sb + FV + 24576 };

    const int qt = blockIdx.x, h = blockIdx.y, b = blockIdx.z;
    const int tid = threadIdx.x;
    const int w = tid >> 5, lane = tid & 31, g = lane >> 2, t = lane & 3;

    /* ---- load Q tile (packed layout, row stride QSTR) ---- */
    const __nv_bfloat16* qb = QKV + (size_t)(b * SS + qt * FBM) * QSTR + h * DKK;
    #pragma unroll
    for (int i = 0; i < 4; i++) {
        int s = tid + i * 256;
        int r = s >> 3, c = s & 7;
        *(uint4*)(fsm + FQP + r * 128 + ((c ^ (r & 7)) << 4)) =
            *(const uint4*)(qb + (size_t)r * QSTR + c * 8);
    }
    __syncthreads();
    uint32_t qf[4][4];
    {
        const int R = w * 16 + (lane & 15);
        const int hh = lane >> 4;
        #pragma unroll
        for (int ks = 0; ks < 4; ks++)
            ldsm4(qf[ks], qp + R * 128 + (((ks * 2 + hh) ^ (R & 7)) << 4));
    }
    __syncthreads();   /* Q smem free -> per-warp P region */

    const __nv_bfloat16* kb = QKV + (size_t)(b * SS) * QSTR + DD + h * DKK;
    const __nv_bfloat16* vb = QKV + (size_t)(b * SS) * QSTR + 2 * DD + h * DKK;
    #define KVSTAGE(buf, kt)                                                   \
    {                                                                          \
        const __nv_bfloat16* kg = kb + (size_t)((kt) * FBN) * QSTR;            \
        const __nv_bfloat16* vg = vb + (size_t)((kt) * FBN) * QSTR;            \
        _Pragma("unroll")                                                      \
        for (int i = 0; i < 2; i++) {                                          \
            int s = tid + i * 256;                                             \
            int r = s >> 3, c = s & 7;                                         \
            cp16s(koff[buf] + r * 128 + ((c ^ (r & 7)) << 4),                  \
                  kg + (size_t)r * QSTR + c * 8);                              \
            cp16s(voff[buf] + r * 128 + ((c ^ (r & 7)) << 4),                  \
                  vg + (size_t)r * QSTR + c * 8);                              \
        }                                                                      \
    }
    KVSTAGE(0, 0);
    asm volatile("cp.async.commit_group;");
    KVSTAGE(1, 1);
    asm volatile("cp.async.commit_group;");

    float oacc[8][4] = {};
    float mrow0 = -1e30f, mrow1 = -1e30f, lrow0 = 0.f, lrow1 = 0.f;
    const int* mp = mask + b * SS;

    const int kbR = (lane & 7) + ((lane >> 4) << 3);
    const int kbH = (lane >> 3) & 1;
    const int vbR = (lane & 7) + (((lane >> 3) & 1) << 3);
    const int vbH = lane >> 4;
    const int paR = lane & 15, paH = lane >> 4;

    for (int kt = 0; kt < FNT; kt++) {
        if (kt + 2 < FNT) KVSTAGE((kt + 2) & 3, kt + 2);
        asm volatile("cp.async.commit_group;");
        asm volatile("cp.async.wait_group 2;");
        __syncthreads();   /* buffer kt&3 visible; bounds warp skew to 1 iter */
        const uint32_t kbuf = koff[kt & 3], vbuf = voff[kt & 3];

        /* ---- S = Q K^T ---- */
        float sacc[8][4] = {};
        #pragma unroll
        for (int ks = 0; ks < 4; ks++) {
            #pragma unroll
            for (int np = 0; np < 4; np++) {
                uint32_t bf[4];
                int R = np * 16 + kbR;
                ldsm4(bf, kbuf + R * 128 + (((ks * 2 + kbH) ^ (R & 7)) << 4));
                mma_bf16(sacc[np * 2 + 0], qf[ks], &bf[0]);
                mma_bf16(sacc[np * 2 + 1], qf[ks], &bf[2]);
            }
        }
        /* ---- scale (exp2 domain) + mask ---- */
        #pragma unroll
        for (int nt = 0; nt < 8; nt++) {
            int mj0 = __ldg(mp + kt * FBN + nt * 8 + 2 * t);
            int mj1 = __ldg(mp + kt * FBN + nt * 8 + 2 * t + 1);
            sacc[nt][0] = mj0 ? sacc[nt][0] * SCALE2 : MASK2;
            sacc[nt][1] = mj1 ? sacc[nt][1] * SCALE2 : MASK2;
            sacc[nt][2] = mj0 ? sacc[nt][2] * SCALE2 : MASK2;
            sacc[nt][3] = mj1 ? sacc[nt][3] * SCALE2 : MASK2;
        }
        /* ---- online softmax (base-2) ---- */
        float tm0 = -1e30f, tm1 = -1e30f;
        #pragma unroll
        for (int nt = 0; nt < 8; nt++) {
            tm0 = fmaxf(tm0, fmaxf(sacc[nt][0], sacc[nt][1]));
            tm1 = fmaxf(tm1, fmaxf(sacc[nt][2], sacc[nt][3]));
        }
        tm0 = fmaxf(tm0, __shfl_xor_sync(0xffffffffu, tm0, 1));
        tm0 = fmaxf(tm0, __shfl_xor_sync(0xffffffffu, tm0, 2));
        tm1 = fmaxf(tm1, __shfl_xor_sync(0xffffffffu, tm1, 1));
        tm1 = fmaxf(tm1, __shfl_xor_sync(0xffffffffu, tm1, 2));
        float mn0 = fmaxf(mrow0, tm0), mn1 = fmaxf(mrow1, tm1);
        float cr0 = ex2(mrow0 - mn0), cr1 = ex2(mrow1 - mn1);
        float sum0 = 0.f, sum1 = 0.f;
        #pragma unroll
        for (int nt = 0; nt < 8; nt++) {
            sacc[nt][0] = ex2(sacc[nt][0] - mn0);
            sacc[nt][1] = ex2(sacc[nt][1] - mn0);
            sacc[nt][2] = ex2(sacc[nt][2] - mn1);
            sacc[nt][3] = ex2(sacc[nt][3] - mn1);
            sum0 += sacc[nt][0] + sacc[nt][1];
            sum1 += sacc[nt][2] + sacc[nt][3];
        }
        sum0 += __shfl_xor_sync(0xffffffffu, sum0, 1);
        sum0 += __shfl_xor_sync(0xffffffffu, sum0, 2);
        sum1 += __shfl_xor_sync(0xffffffffu, sum1, 1);
        sum1 += __shfl_xor_sync(0xffffffffu, sum1, 2);
        lrow0 = lrow0 * cr0 + sum0; mrow0 = mn0;
        lrow1 = lrow1 * cr1 + sum1; mrow1 = mn1;
        #pragma unroll
        for (int nt = 0; nt < 8; nt++) {
            oacc[nt][0] *= cr0; oacc[nt][1] *= cr0;
            oacc[nt][2] *= cr1; oacc[nt][3] *= cr1;
        }
        /* ---- P (bf16) -> per-warp smem region ---- */
        {
            const uint32_t pr0 = qp + (w * 16 + g) * 128;
            const uint32_t pr1 = qp + (w * 16 + g + 8) * 128;
            #pragma unroll
            for (int nt = 0; nt < 8; nt++) {
                uint32_t off = ((nt ^ g) << 4) + t * 4;
                *(uint32_t*)(fsm + (pr0 + off - sb)) = pack_bf16(sacc[nt][0], sacc[nt][1]);
                *(uint32_t*)(fsm + (pr1 + off - sb)) = pack_bf16(sacc[nt][2], sacc[nt][3]);
            }
        }
        __syncwarp();
        /* ---- O += P V ---- */
        #pragma unroll
        for (int ks = 0; ks < 4; ks++) {
            uint32_t pf[4];
            {
                int R = w * 16 + paR;
                ldsm4(pf, qp + R * 128 + (((ks * 2 + paH) ^ (R & 7)) << 4));
            }
            #pragma unroll
            for (int np = 0; np < 4; np++) {
                uint32_t bv[4];
                int R = ks * 16 + vbR;
                ldsm4t(bv, vbuf + R * 128 + (((np * 2 + vbH) ^ (R & 7)) << 4));
                mma_bf16(oacc[np * 2 + 0], pf, &bv[0]);
                mma_bf16(oacc[np * 2 + 1], pf, &bv[2]);
            }
        }
    }
    #undef KVSTAGE

    /* epilogue: normalize, store fp16 */
    float inv0 = 1.f / lrow0, inv1 = 1.f / lrow1;
    __half* ob = O + (size_t)(b * SS + qt * FBM) * DD + h * DKK;
    int r0 = w * 16 + g;
    #pragma unroll
    for (int nt = 0; nt < 8; nt++) {
        int col = nt * 8 + 2 * t;
        *(uint32_t*)(ob + (size_t)r0 * DD + col) =
            pack_fp16(oacc[nt][0] * inv0, oacc[nt][1] * inv0);
        *(uint32_t*)(ob + (size_t)(r0 + 8) * DD + col) =
            pack_fp16(oacc[nt][2] * inv1, oacc[nt][3] * inv1);
    }
}

/* ---------------- host orchestration (graph-capturable) ------------------- */
extern "C" void kernel_launch(void* const* d_in, const int* in_sizes, int n_in,
                              void* d_out, int out_size) {
    (void)in_sizes; (void)n_in; (void)out_size;
    const float* x    = (const float*)d_in[0];
    const int*   mask = (const int*)  d_in[1];
    const float* wq   = (const float*)d_in[2];
    const float* bq   = (const float*)d_in[3];
    const float* wk   = (const float*)d_in[4];
    const float* bk   = (const float*)d_in[5];
    const float* wv   = (const float*)d_in[6];
    const float* bv   = (const float*)d_in[7];
    const float* wo   = (const float*)d_in[8];
    const float* bo   = (const float*)d_in[9];
    const float* w1   = (const float*)d_in[10];
    const float* b1   = (const float*)d_in[11];
    const float* w2   = (const float*)d_in[12];
    const float* b2   = (const float*)d_in[13];
    const float* a1   = (const float*)d_in[14];
    const float* c1   = (const float*)d_in[15];
    const float* a2   = (const float*)d_in[16];
    const float* c2   = (const float*)d_in[17];
    float* out = (float*)d_out;

    float *h, *bqkv;
    __nv_bfloat16 *ln1b, *qkvb, *wqkvb;
    __half *attnh, *ln2h, *ffnh, *woh, *w1h, *w2h;
    cudaGetSymbolAddress((void**)&ln1b,  g_ln1b);
    cudaGetSymbolAddress((void**)&qkvb,  g_qkvb);
    cudaGetSymbolAddress((void**)&attnh, g_attnh);
    cudaGetSymbolAddress((void**)&h,     g_h);
    cudaGetSymbolAddress((void**)&ln2h,  g_ln2h);
    cudaGetSymbolAddress((void**)&ffnh,  g_ffnh);
    cudaGetSymbolAddress((void**)&wqkvb, g_wqkvb);
    cudaGetSymbolAddress((void**)&bqkv,  g_bqkv);
    cudaGetSymbolAddress((void**)&woh,   g_woh);
    cudaGetSymbolAddress((void**)&w1h,   g_w1h);
    cudaGetSymbolAddress((void**)&w2h,   g_w2h);

    cudaFuncSetAttribute(flash_bf16,
                         cudaFuncAttributeMaxDynamicSharedMemorySize, FSMEM);
    cudaFuncSetAttribute(gemm16<false,false,false,1>,
                         cudaFuncAttributeMaxDynamicSharedMemorySize, GSMEM);
    cudaFuncSetAttribute(gemm16<false,true,true,0>,
                         cudaFuncAttributeMaxDynamicSharedMemorySize, GSMEM);
    cudaFuncSetAttribute(gemm16<true,false,true,2>,
                         cudaFuncAttributeMaxDynamicSharedMemorySize, GSMEM);

    /* weight pre-rounding: packed QKV -> bf16; wo/w1/w2 -> fp16 */
    cvt_bf16_kernel<<<(DD*DD/4)/256,   256>>>(wq, wqkvb,             DD*DD/4);
    cvt_bf16_kernel<<<(DD*DD/4)/256,   256>>>(wk, wqkvb + DD*DD,     DD*DD/4);
    cvt_bf16_kernel<<<(DD*DD/4)/256,   256>>>(wv, wqkvb + 2*DD*DD,   DD*DD/4);
    cvt_fp16_kernel<<<(DD*DD/4)/256,   256>>>(wo, woh, DD*DD/4);
    cvt_fp16_kernel<<<(DFFN*DD/4)/256, 256>>>(w1, w1h, DFFN*DD/4);
    cvt_fp16_kernel<<<(DFFN*DD/4)/256, 256>>>(w2, w2h, DFFN*DD/4);
    /* packed bias (async D2D copies are graph-capturable) */
    cudaMemcpyAsync(bqkv,          bq, DD*sizeof(float), cudaMemcpyDeviceToDevice);
    cudaMemcpyAsync(bqkv + DD,     bk, DD*sizeof(float), cudaMemcpyDeviceToDevice);
    cudaMemcpyAsync(bqkv + 2*DD,   bv, DD*sizeof(float), cudaMemcpyDeviceToDevice);

    /* LN1 -> bf16 */
    ln_kernel<1><<<NTOK, 256>>>(x, a1, c1, ln1b);
    /* fused QKV projection (bf16 mma) -> packed bf16 [NTOK, 3*DD] */
    gemm16<false,false,false,1><<<dim3(QSTR / TBN, NTOK / TBM), 256, GSMEM>>>(
        (const uint16_t*)ln1b, (const uint16_t*)wqkvb, bqkv, nullptr,
        qkvb, NTOK, QSTR, DD);
    /* attention (packed bf16 in, fp16 out) */
    flash_bf16<<<dim3(SS / FBM, HH, BB), 256, FSMEM>>>(qkvb, mask, attnh);
    /* h = x + attn @ wo^T + bo  (fp16 mma, fp32 out) */
    dim3 gq(DD / TBN, NTOK / TBM);
    gemm16<false,true,true,0><<<gq, 256, GSMEM>>>(
        (const uint16_t*)attnh, (const uint16_t*)woh, bo, x, h, NTOK, DD, DD);
    /* LN2 -> fp16 */
    ln_kernel<2><<<NTOK, 256>>>(h, a2, c2, ln2h);
    /* ffn = relu(ln2 @ w1^T + b1)  (fp16 mma, fp16 out) */
    gemm16<true,false,true,2><<<dim3(DFFN / TBN, NTOK / TBM), 256, GSMEM>>>(
        (const uint16_t*)ln2h, (const uint16_t*)w1h, b1, nullptr, ffnh, NTOK, DFFN, DD);
    /* out = h + ffn @ w2^T + b2  (fp16 mma, fp32 out) */
    gemm16<false,true,true,0><<<gq, 256, GSMEM>>>(
        (const uint16_t*)ffnh, (const uint16_t*)w2h, b2, h, out, NTOK, DD, DFFN);
}